// round 2
// baseline (speedup 1.0000x reference)
#include <cuda_runtime.h>

#define BATCH 8
#define DIM   384
#define CC    96
#define HIN   128
#define HQ    32
#define NN    1024
#define NH    4
#define HD    24
#define TBL   3969   // (2*32-1)^2
#define EPSI  1e-5f

// ---------------- scratch (device globals: no allocation allowed) ----------------
__device__ __align__(16) float g_convp[BATCH*DIM*NN];
__device__ __align__(16) float g_pmax [BATCH*DIM*NN];
__device__ __align__(16) float g_pavg [BATCH*DIM*NN];
__device__ __align__(16) float g_xq   [BATCH*NN*CC];
__device__ __align__(16) float g_tmax [BATCH*NN*CC];
__device__ __align__(16) float g_tavg [BATCH*NN*CC];
__device__ __align__(16) float g_q    [BATCH*NN*CC];
__device__ __align__(16) float g_kv1  [BATCH*NN*2*CC];
__device__ __align__(16) float g_kv2  [BATCH*NN*2*CC];
__device__ __align__(16) float g_o1   [BATCH*NN*CC];
__device__ __align__(16) float g_o2   [BATCH*NN*CC];
__device__ __align__(16) float g_small[BATCH*DIM*NN];
__device__ __align__(16) float g_W2   [CC*DIM];
__device__ __align__(16) float g_bb   [DIM];

__device__ __forceinline__ float relu6f(float v) { return fminf(fmaxf(v, 0.f), 6.f); }

// ---------------- fold w_proj @ w_out^T and biases ----------------
__global__ void k_prep(const float* __restrict__ wproj, const float* __restrict__ bproj,
                       const float* __restrict__ wout,  const float* __restrict__ bout) {
    int o = blockIdx.x;          // 0..383
    int i = threadIdx.x;         // 0..95
    float acc = 0.f;
    #pragma unroll 8
    for (int c = 0; c < CC; c++) acc += wproj[i*CC + c] * wout[o*CC + c];
    g_W2[i*DIM + o] = acc;
    if (i == 0) {
        float s = 0.f;
        for (int c = 0; c < CC; c++) s += bproj[c] * wout[o*CC + c];
        g_bb[o] = bout[o] + 2.f * s;
    }
}

// ---------------- stage1: per input channel d, per 4x4 block: max, avg, conv-partial ----------------
__global__ __launch_bounds__(256) void k_stage1(const float* __restrict__ x,
                                                const float* __restrict__ w_le) {
    int part = blockIdx.x;        // 0..3
    int d    = blockIdx.y;        // 0..383
    int b    = blockIdx.z;        // 0..7
    int p  = part*256 + threadIdx.x;   // 0..1023 position n
    int oh = p >> 5, ow = p & 31;

    // w_le [96,4,4,4]: c = d>>2, ic = d&3
    const float* w = w_le + (size_t)(d >> 2)*64 + (size_t)(d & 3)*16;
    float wr[16];
    #pragma unroll
    for (int i = 0; i < 16; i++) wr[i] = w[i];

    const float* xp = x + (((size_t)(b*DIM + d)*HIN) + 4*oh)*HIN + 4*ow;
    float mx = -1e30f, sm = 0.f, cv = 0.f;
    #pragma unroll
    for (int kh = 0; kh < 4; kh++) {
        float4 v = *(const float4*)(xp + (size_t)kh*HIN);
        mx = fmaxf(mx, fmaxf(fmaxf(v.x, v.y), fmaxf(v.z, v.w)));
        sm += v.x + v.y + v.z + v.w;
        cv += v.x*wr[kh*4+0] + v.y*wr[kh*4+1] + v.z*wr[kh*4+2] + v.w*wr[kh*4+3];
    }
    size_t idx = (size_t)(b*DIM + d)*NN + p;
    g_pmax [idx] = mx;
    g_pavg [idx] = sm * (1.f/16.f);
    g_convp[idx] = cv;
}

// ---------------- stage2: combine groups of 4, bias+BN+ReLU6, transpose to [B,N,C] ----------------
__global__ __launch_bounds__(256) void k_stage2(
    const float* __restrict__ b_le,  const float* __restrict__ bn_le,
    const float* __restrict__ w_max, const float* __restrict__ b_max, const float* __restrict__ bn_max,
    const float* __restrict__ w_avg, const float* __restrict__ b_avg, const float* __restrict__ bn_avg)
{
    int c = blockIdx.x;          // 0..95
    int b = blockIdx.y;          // 0..7

    float sle = bn_le [0*CC+c] * rsqrtf(bn_le [3*CC+c] + EPSI);
    float tle = bn_le [1*CC+c] - bn_le [2*CC+c]*sle;
    float smx = bn_max[0*CC+c] * rsqrtf(bn_max[3*CC+c] + EPSI);
    float tmx = bn_max[1*CC+c] - bn_max[2*CC+c]*smx;
    float sav = bn_avg[0*CC+c] * rsqrtf(bn_avg[3*CC+c] + EPSI);
    float tav = bn_avg[1*CC+c] - bn_avg[2*CC+c]*sav;

    float wm0 = w_max[c*4+0], wm1 = w_max[c*4+1], wm2 = w_max[c*4+2], wm3 = w_max[c*4+3];
    float wa0 = w_avg[c*4+0], wa1 = w_avg[c*4+1], wa2 = w_avg[c*4+2], wa3 = w_avg[c*4+3];
    float ble = b_le[c], bmx = b_max[c], bav = b_avg[c];

    for (int n = threadIdx.x; n < NN; n += 256) {
        size_t base = (size_t)(b*DIM + 4*c)*NN + n;
        float conv = g_convp[base] + g_convp[base+NN] + g_convp[base+2*NN] + g_convp[base+3*NN];
        float xq = relu6f((conv + ble)*sle + tle);
        float pm = g_pmax[base]*wm0 + g_pmax[base+NN]*wm1 + g_pmax[base+2*NN]*wm2 + g_pmax[base+3*NN]*wm3;
        float tm = relu6f((pm + bmx)*smx + tmx);
        float pa = g_pavg[base]*wa0 + g_pavg[base+NN]*wa1 + g_pavg[base+2*NN]*wa2 + g_pavg[base+3*NN]*wa3;
        float ta = relu6f((pa + bav)*sav + tav);
        size_t oidx = (size_t)(b*NN + n)*CC + c;
        g_xq  [oidx] = xq;
        g_tmax[oidx] = tm;
        g_tavg[oidx] = ta;
    }
}

// ---------------- small GEMM: [8192,96] @ W[96, 96-col slice] -> out slice ----------------
// which: 0 = q (g_xq -> g_q, ld 96), 1 = kv1 (g_tmax -> g_kv1, ld 192), 2 = kv2 (g_tavg -> g_kv2, ld 192)
__global__ __launch_bounds__(256) void k_gemm(int which, const float* __restrict__ W,
                                              int Wld, int col0, float scale) {
    __shared__ __align__(16) float inS[32*CC];     // 12 KB
    __shared__ __align__(16) float Ws [CC*CC];     // 36 KB
    const float* in; float* out; int outld;
    if (which == 0)      { in = g_xq;   out = g_q;   outld = CC;   }
    else if (which == 1) { in = g_tmax; out = g_kv1; outld = 2*CC; }
    else                 { in = g_tavg; out = g_kv2; outld = 2*CC; }

    int row0 = blockIdx.x * 32;
    for (int i = threadIdx.x; i < 32*CC; i += 256) inS[i] = in[(size_t)row0*CC + i];
    for (int i = threadIdx.x; i < CC*CC; i += 256) {
        int k = i / CC, j = i % CC;
        Ws[i] = W[(size_t)k*Wld + col0 + j];
    }
    __syncthreads();

    for (int pos = threadIdx.x*4; pos < 32*CC; pos += 1024) {
        int r = pos / CC, j = pos % CC;
        float4 acc = make_float4(0.f, 0.f, 0.f, 0.f);
        const float* ir = inS + r*CC;
        #pragma unroll
        for (int k = 0; k < CC; k++) {
            float a  = ir[k];
            float4 w = *(const float4*)(Ws + k*CC + j);
            acc.x += a*w.x; acc.y += a*w.y; acc.z += a*w.z; acc.w += a*w.w;
        }
        acc.x *= scale; acc.y *= scale; acc.z *= scale; acc.w *= scale;
        *(float4*)(out + (size_t)(row0 + r)*outld + col0 + j) = acc;
    }
}

// ---------------- attention: lane-per-query-row, flash-style online softmax ----------------
__global__ __launch_bounds__(64) void k_attn(const float* __restrict__ bias_table) {
    int chunk = blockIdx.x;               // 0..15 : 64 rows each
    int bh    = blockIdx.y;               // b*NH + h
    int br    = blockIdx.z;               // branch
    int b = bh >> 2, h = bh & 3;
    const float* kv = br ? g_kv2 : g_kv1;
    float*       oo = br ? g_o2  : g_o1;

    // NOTE: float4-accessed arrays FIRST (16B-aligned base), odd-sized biasS LAST.
    __shared__ __align__(16) float kT[32*HD];           // 3 KB
    __shared__ __align__(16) float vT[32*HD];           // 3 KB
    __shared__ float biasS[TBL];                        // 15.9 KB

    int tid = threadIdx.x;                // 0..63
    for (int i = tid; i < TBL; i += 64) biasS[i] = bias_table[(size_t)i*NH + h];

    int n  = chunk*64 + tid;              // each lane owns one query row
    int yn = n >> 5, xn = n & 31;

    float qr[HD];
    const float* qp = g_q + (size_t)(b*NN + n)*CC + h*HD;
    #pragma unroll
    for (int i = 0; i < 6; i++) {
        float4 v = ((const float4*)qp)[i];
        qr[4*i+0] = v.x; qr[4*i+1] = v.y; qr[4*i+2] = v.z; qr[4*i+3] = v.w;
    }

    float m = -1e30f, l = 0.f;
    float o[HD];
    #pragma unroll
    for (int d = 0; d < HD; d++) o[d] = 0.f;

    __syncthreads();  // bias table ready

    for (int kt = 0; kt < 32; kt++) {
        // cooperative tile load: 32 keys x 24 floats for k and v
        for (int i = tid; i < 32*6; i += 64) {
            int key = i / 6, g4 = i % 6;
            const float* rowp = kv + (size_t)(b*NN + kt*32 + key)*(2*CC) + h*HD;
            ((float4*)kT)[i] = *(const float4*)(rowp + g4*4);
            ((float4*)vT)[i] = *(const float4*)(rowp + CC + g4*4);
        }
        __syncthreads();

        #pragma unroll
        for (int c16 = 0; c16 < 2; c16++) {
            float s[16];
            #pragma unroll
            for (int j = 0; j < 16; j++) {
                const float* kr = kT + (c16*16 + j)*HD;
                float acc = 0.f;
                #pragma unroll
                for (int d = 0; d < HD; d++) acc += qr[d]*kr[d];
                int mkey = kt*32 + c16*16 + j;
                int ym = mkey >> 5, xm = mkey & 31;
                int tix = (yn - ym + 31)*63 + (xn - xm + 31);
                s[j] = acc + biasS[tix];
            }
            float mc = s[0];
            #pragma unroll
            for (int j = 1; j < 16; j++) mc = fmaxf(mc, s[j]);
            float mnew  = fmaxf(m, mc);
            float alpha = __expf(m - mnew);
            l *= alpha;
            #pragma unroll
            for (int d = 0; d < HD; d++) o[d] *= alpha;
            #pragma unroll
            for (int j = 0; j < 16; j++) {
                float p = __expf(s[j] - mnew);
                l += p;
                const float* vr = vT + (c16*16 + j)*HD;
                #pragma unroll
                for (int d = 0; d < HD; d++) o[d] += p*vr[d];
            }
            m = mnew;
        }
        __syncthreads();
    }

    float inv = 1.f / l;
    float* op = oo + (size_t)(b*NN + n)*CC + h*HD;
    #pragma unroll
    for (int i = 0; i < 6; i++) {
        float4 v = make_float4(o[4*i+0]*inv, o[4*i+1]*inv, o[4*i+2]*inv, o[4*i+3]*inv);
        ((float4*)op)[i] = v;
    }
}

// ---------------- (o1+o2) @ W2 + bb -> [B,384,32,32] ----------------
__global__ __launch_bounds__(256) void k_proj() {
    int nt = blockIdx.x;     // 0..31
    int b  = blockIdx.y;     // 0..7
    int n0 = nt * 32;
    __shared__ __align__(16) float W2c[CC*64];     // 24 KB
    __shared__ float s[32*97];                     // padded rows, 12.4 KB

    int tid = threadIdx.x;
    for (int i = tid; i < 32*CC; i += 256) {
        int r = i / CC, c = i % CC;
        size_t idx = (size_t)(b*NN + n0 + r)*CC + c;
        s[r*97 + c] = g_o1[idx] + g_o2[idx];
    }

    int r     = tid & 31;
    int olane = tid >> 5;    // 0..7
    for (int ch = 0; ch < 6; ch++) {
        __syncthreads();
        for (int i = tid; i < CC*64; i += 256) {
            int c = i >> 6, j = i & 63;
            W2c[i] = g_W2[(size_t)c*DIM + ch*64 + j];
        }
        __syncthreads();
        #pragma unroll
        for (int jj = 0; jj < 8; jj++) {
            int j = olane + jj*8;
            float acc = g_bb[ch*64 + j];
            #pragma unroll 8
            for (int c = 0; c < CC; c++) acc += s[r*97 + c] * W2c[c*64 + j];
            g_small[((size_t)(b*DIM) + ch*64 + j)*NN + n0 + r] = acc;
        }
    }
}

// ---------------- bilinear x4 upsample, align_corners=True ----------------
__global__ __launch_bounds__(256) void k_upsample(float* __restrict__ out) {
    int plane = blockIdx.x;  // b*DIM + channel
    __shared__ float pl[NN];
    for (int i = threadIdx.x; i < NN; i += 256) pl[i] = g_small[(size_t)plane*NN + i];
    __syncthreads();

    const float sc = 31.f / 127.f;
    float* op = out + (size_t)plane*128*128;
    for (int idx = threadIdx.x; idx < 128*128; idx += 256) {
        int yo = idx >> 7, xo = idx & 127;
        float fy = yo * sc; int y0 = (int)fy; float wy = fy - y0; int y1 = min(y0+1, 31);
        float fx = xo * sc; int x0 = (int)fx; float wx = fx - x0; int x1 = min(x0+1, 31);
        float v00 = pl[y0*32+x0], v01 = pl[y0*32+x1];
        float v10 = pl[y1*32+x0], v11 = pl[y1*32+x1];
        float top = v00 + (v01 - v00)*wx;
        float bot = v10 + (v11 - v10)*wx;
        op[idx] = top + (bot - top)*wy;
    }
}

// ---------------- launch ----------------
extern "C" void kernel_launch(void* const* d_in, const int* in_sizes, int n_in,
                              void* d_out, int out_size) {
    const float* x        = (const float*)d_in[0];
    const float* w_le     = (const float*)d_in[1];
    const float* b_le     = (const float*)d_in[2];
    const float* bn_le    = (const float*)d_in[3];
    const float* w_max    = (const float*)d_in[4];
    const float* b_max    = (const float*)d_in[5];
    const float* bn_max   = (const float*)d_in[6];
    const float* w_avg    = (const float*)d_in[7];
    const float* b_avg    = (const float*)d_in[8];
    const float* bn_avg   = (const float*)d_in[9];
    const float* bias_tab = (const float*)d_in[10];
    const float* w_q      = (const float*)d_in[11];
    const float* w_kv     = (const float*)d_in[12];
    const float* w_proj   = (const float*)d_in[13];
    const float* b_proj   = (const float*)d_in[14];
    const float* w_out    = (const float*)d_in[15];
    const float* b_out    = (const float*)d_in[16];
    float* out = (float*)d_out;

    const float qscale = 0.20412414523193154f;   // 1/sqrt(24)

    k_prep  <<<DIM, CC>>>(w_proj, b_proj, w_out, b_out);
    k_stage1<<<dim3(4, DIM, BATCH), 256>>>(x, w_le);
    k_stage2<<<dim3(CC, BATCH), 256>>>(b_le, bn_le, w_max, b_max, bn_max, w_avg, b_avg, bn_avg);

    k_gemm<<<256, 256>>>(0, w_q,  CC,    0, qscale);  // q
    k_gemm<<<256, 256>>>(1, w_kv, 2*CC,  0, 1.f);     // k1
    k_gemm<<<256, 256>>>(1, w_kv, 2*CC, CC, 1.f);     // v1
    k_gemm<<<256, 256>>>(2, w_kv, 2*CC,  0, 1.f);     // k2
    k_gemm<<<256, 256>>>(2, w_kv, 2*CC, CC, 1.f);     // v2

    k_attn<<<dim3(16, NH*BATCH, 2), 64>>>(bias_tab);
    k_proj<<<dim3(32, BATCH), 256>>>();
    k_upsample<<<BATCH*DIM, 256>>>(out);
}

// round 3
// speedup vs baseline: 1.0413x; 1.0413x over previous
#include <cuda_runtime.h>

#define BATCH 8
#define DIM   384
#define CC    96
#define HIN   128
#define HQ    32
#define NN    1024
#define NH    4
#define HD    24
#define TBL   3969   // (2*32-1)^2
#define EPSI  1e-5f

typedef unsigned long long u64;

// ---------------- scratch (device globals: no allocation allowed) ----------------
__device__ __align__(16) float g_convp[BATCH*DIM*NN];
__device__ __align__(16) float g_pmax [BATCH*DIM*NN];
__device__ __align__(16) float g_pavg [BATCH*DIM*NN];
__device__ __align__(16) float g_xq   [BATCH*NN*CC];
__device__ __align__(16) float g_tmax [BATCH*NN*CC];
__device__ __align__(16) float g_tavg [BATCH*NN*CC];
__device__ __align__(16) float g_q    [BATCH*NN*CC];
__device__ __align__(16) float g_kv1  [BATCH*NN*2*CC];
__device__ __align__(16) float g_kv2  [BATCH*NN*2*CC];
__device__ __align__(16) float g_o1   [BATCH*NN*CC];
__device__ __align__(16) float g_o2   [BATCH*NN*CC];
__device__ __align__(16) float g_small[BATCH*DIM*NN];
__device__ __align__(16) float g_W2   [CC*DIM];
__device__ __align__(16) float g_bb   [DIM];

__device__ __forceinline__ float relu6f(float v) { return fminf(fmaxf(v, 0.f), 6.f); }

// ---- packed f32x2 helpers (Blackwell FFMA2 — ptxas won't auto-fuse; PTX only) ----
__device__ __forceinline__ u64 pack2(float a, float b) {
    u64 r; asm("mov.b64 %0, {%1, %2};" : "=l"(r) : "f"(a), "f"(b)); return r;
}
__device__ __forceinline__ void unpack2(u64 v, float& a, float& b) {
    asm("mov.b64 {%0, %1}, %2;" : "=f"(a), "=f"(b) : "l"(v));
}
__device__ __forceinline__ u64 fma2(u64 a, u64 b, u64 c) {
    u64 d; asm("fma.rn.f32x2 %0, %1, %2, %3;" : "=l"(d) : "l"(a), "l"(b), "l"(c)); return d;
}
__device__ __forceinline__ u64 mul2(u64 a, u64 b) {
    u64 d; asm("mul.rn.f32x2 %0, %1, %2;" : "=l"(d) : "l"(a), "l"(b)); return d;
}

// ---- MUFU-free exp: exp2 via magic rounding + degree-5 poly, all on fma/alu pipes ----
__device__ __forceinline__ float fast_exp(float x) {
    float t  = fmaxf(x * 1.4426950408889634f, -125.0f);   // log2(e), clamp for bit-scale
    float z  = t + 12582912.0f;                           // 2^23+2^22: round-to-nearest int
    int   zi = __float_as_int(z);
    float fl = z - 12582912.0f;
    float f  = t - fl;                                    // f in [-0.5, 0.5]
    float p  = 1.3333558146e-3f;
    p = fmaf(p, f, 9.6181291076e-3f);
    p = fmaf(p, f, 5.5504108665e-2f);
    p = fmaf(p, f, 2.4022650696e-1f);
    p = fmaf(p, f, 6.9314718056e-1f);
    p = fmaf(p, f, 1.0f);
    int sb = (zi - 0x4B3FFF81) << 23;                     // (round(t)+127)<<23
    return p * __int_as_float(sb);
}

// ---------------- fold w_proj @ w_out^T and biases ----------------
__global__ void k_prep(const float* __restrict__ wproj, const float* __restrict__ bproj,
                       const float* __restrict__ wout,  const float* __restrict__ bout) {
    int o = blockIdx.x;          // 0..383
    int i = threadIdx.x;         // 0..95
    float acc = 0.f;
    #pragma unroll 8
    for (int c = 0; c < CC; c++) acc += wproj[i*CC + c] * wout[o*CC + c];
    g_W2[i*DIM + o] = acc;
    if (i == 0) {
        float s = 0.f;
        for (int c = 0; c < CC; c++) s += bproj[c] * wout[o*CC + c];
        g_bb[o] = bout[o] + 2.f * s;
    }
}

// ---------------- stage1: per input channel d, per 4x4 block: max, avg, conv-partial ----------------
__global__ __launch_bounds__(256) void k_stage1(const float* __restrict__ x,
                                                const float* __restrict__ w_le) {
    int part = blockIdx.x;        // 0..3
    int d    = blockIdx.y;        // 0..383
    int b    = blockIdx.z;        // 0..7
    int p  = part*256 + threadIdx.x;   // 0..1023 position n
    int oh = p >> 5, ow = p & 31;

    const float* w = w_le + (size_t)(d >> 2)*64 + (size_t)(d & 3)*16;
    float wr[16];
    #pragma unroll
    for (int i = 0; i < 16; i++) wr[i] = w[i];

    const float* xp = x + (((size_t)(b*DIM + d)*HIN) + 4*oh)*HIN + 4*ow;
    float mx = -1e30f, sm = 0.f, cv = 0.f;
    #pragma unroll
    for (int kh = 0; kh < 4; kh++) {
        float4 v = *(const float4*)(xp + (size_t)kh*HIN);
        mx = fmaxf(mx, fmaxf(fmaxf(v.x, v.y), fmaxf(v.z, v.w)));
        sm += v.x + v.y + v.z + v.w;
        cv += v.x*wr[kh*4+0] + v.y*wr[kh*4+1] + v.z*wr[kh*4+2] + v.w*wr[kh*4+3];
    }
    size_t idx = (size_t)(b*DIM + d)*NN + p;
    g_pmax [idx] = mx;
    g_pavg [idx] = sm * (1.f/16.f);
    g_convp[idx] = cv;
}

// ---------------- stage2: combine groups of 4, bias+BN+ReLU6, transpose to [B,N,C] ----------------
__global__ __launch_bounds__(256) void k_stage2(
    const float* __restrict__ b_le,  const float* __restrict__ bn_le,
    const float* __restrict__ w_max, const float* __restrict__ b_max, const float* __restrict__ bn_max,
    const float* __restrict__ w_avg, const float* __restrict__ b_avg, const float* __restrict__ bn_avg)
{
    int c = blockIdx.x;          // 0..95
    int b = blockIdx.y;          // 0..7

    float sle = bn_le [0*CC+c] * rsqrtf(bn_le [3*CC+c] + EPSI);
    float tle = bn_le [1*CC+c] - bn_le [2*CC+c]*sle;
    float smx = bn_max[0*CC+c] * rsqrtf(bn_max[3*CC+c] + EPSI);
    float tmx = bn_max[1*CC+c] - bn_max[2*CC+c]*smx;
    float sav = bn_avg[0*CC+c] * rsqrtf(bn_avg[3*CC+c] + EPSI);
    float tav = bn_avg[1*CC+c] - bn_avg[2*CC+c]*sav;

    float wm0 = w_max[c*4+0], wm1 = w_max[c*4+1], wm2 = w_max[c*4+2], wm3 = w_max[c*4+3];
    float wa0 = w_avg[c*4+0], wa1 = w_avg[c*4+1], wa2 = w_avg[c*4+2], wa3 = w_avg[c*4+3];
    float ble = b_le[c], bmx = b_max[c], bav = b_avg[c];

    for (int n = threadIdx.x; n < NN; n += 256) {
        size_t base = (size_t)(b*DIM + 4*c)*NN + n;
        float conv = g_convp[base] + g_convp[base+NN] + g_convp[base+2*NN] + g_convp[base+3*NN];
        float xq = relu6f((conv + ble)*sle + tle);
        float pm = g_pmax[base]*wm0 + g_pmax[base+NN]*wm1 + g_pmax[base+2*NN]*wm2 + g_pmax[base+3*NN]*wm3;
        float tm = relu6f((pm + bmx)*smx + tmx);
        float pa = g_pavg[base]*wa0 + g_pavg[base+NN]*wa1 + g_pavg[base+2*NN]*wa2 + g_pavg[base+3*NN]*wa3;
        float ta = relu6f((pa + bav)*sav + tav);
        size_t oidx = (size_t)(b*NN + n)*CC + c;
        g_xq  [oidx] = xq;
        g_tmax[oidx] = tm;
        g_tavg[oidx] = ta;
    }
}

// ---------------- fused GEMMs: all 5 [8192,96]x[96,96] slices in ONE launch ----------------
__global__ __launch_bounds__(256) void k_gemm_all(const float* __restrict__ wq,
                                                  const float* __restrict__ wkv,
                                                  float qscale) {
    __shared__ __align__(16) float inS[32*CC];     // 12 KB
    __shared__ __align__(16) float Ws [CC*CC];     // 36 KB

    int slice = blockIdx.y;
    const float* in; float* out; const float* W; int Wld, col0, outld; float scale = 1.f;
    switch (slice) {
        case 0:  in = g_xq;   out = g_q;   W = wq;  Wld = CC;   col0 = 0;  outld = CC;   scale = qscale; break;
        case 1:  in = g_tmax; out = g_kv1; W = wkv; Wld = 2*CC; col0 = 0;  outld = 2*CC; break;
        case 2:  in = g_tmax; out = g_kv1; W = wkv; Wld = 2*CC; col0 = CC; outld = 2*CC; break;
        case 3:  in = g_tavg; out = g_kv2; W = wkv; Wld = 2*CC; col0 = 0;  outld = 2*CC; break;
        default: in = g_tavg; out = g_kv2; W = wkv; Wld = 2*CC; col0 = CC; outld = 2*CC; break;
    }

    int row0 = blockIdx.x * 32;
    for (int i = threadIdx.x; i < 32*CC; i += 256) inS[i] = in[(size_t)row0*CC + i];
    for (int i = threadIdx.x; i < CC*CC; i += 256) {
        int k = i / CC, j = i % CC;
        Ws[i] = W[(size_t)k*Wld + col0 + j];
    }
    __syncthreads();

    for (int pos = threadIdx.x*4; pos < 32*CC; pos += 1024) {
        int r = pos / CC, j = pos % CC;
        float4 acc = make_float4(0.f, 0.f, 0.f, 0.f);
        const float* ir = inS + r*CC;
        #pragma unroll
        for (int k = 0; k < CC; k++) {
            float a  = ir[k];
            float4 w = *(const float4*)(Ws + k*CC + j);
            acc.x += a*w.x; acc.y += a*w.y; acc.z += a*w.z; acc.w += a*w.w;
        }
        acc.x *= scale; acc.y *= scale; acc.z *= scale; acc.w *= scale;
        *(float4*)(out + (size_t)(row0 + r)*outld + col0 + j) = acc;
    }
}

// ---------------- attention: lane-per-query-row, flash softmax, f32x2 packed math ----------------
__global__ __launch_bounds__(128) void k_attn(const float* __restrict__ bias_table) {
    int chunk = blockIdx.x;               // 0..7 : 128 rows each
    int bh    = blockIdx.y;               // b*NH + h
    int br    = blockIdx.z;               // branch
    int b = bh >> 2, h = bh & 3;
    const float* kv = br ? g_kv2 : g_kv1;
    float*       oo = br ? g_o2  : g_o1;

    __shared__ __align__(16) float kT[32*HD];           // 3 KB
    __shared__ __align__(16) float vT[32*HD];           // 3 KB
    __shared__ float biasS[TBL];                        // 15.9 KB

    int tid = threadIdx.x;                // 0..127
    for (int i = tid; i < TBL; i += 128) biasS[i] = bias_table[(size_t)i*NH + h];

    int n  = chunk*128 + tid;             // each lane owns one query row
    int yn = n >> 5, xn = n & 31;

    // q packed: 12 x f32x2 (8B-aligned global loads)
    u64 q2[12];
    {
        const u64* qp = (const u64*)(g_q + (size_t)(b*NN + n)*CC + h*HD);
        #pragma unroll
        for (int i = 0; i < 12; i++) q2[i] = qp[i];
    }

    float m = -1e30f, l = 0.f;
    u64 o2[12];
    u64 zz = pack2(0.f, 0.f);
    #pragma unroll
    for (int i = 0; i < 12; i++) o2[i] = zz;

    __syncthreads();  // bias table ready

    for (int kt = 0; kt < 32; kt++) {
        for (int i = tid; i < 32*6; i += 128) {
            int key = i / 6, g4 = i % 6;
            const float* rowp = kv + (size_t)(b*NN + kt*32 + key)*(2*CC) + h*HD;
            ((float4*)kT)[i] = *(const float4*)(rowp + g4*4);
            ((float4*)vT)[i] = *(const float4*)(rowp + CC + g4*4);
        }
        __syncthreads();

        #pragma unroll
        for (int c16 = 0; c16 < 2; c16++) {
            float s[16];
            #pragma unroll
            for (int j = 0; j < 16; j++) {
                const u64* kr = (const u64*)(kT + (c16*16 + j)*HD);
                u64 acc2 = zz;
                #pragma unroll
                for (int d = 0; d < 12; d++) acc2 = fma2(q2[d], kr[d], acc2);
                float alo, ahi; unpack2(acc2, alo, ahi);
                int mkey = kt*32 + c16*16 + j;
                int ym = mkey >> 5, xm = mkey & 31;
                int tix = (yn - ym + 31)*63 + (xn - xm + 31);
                s[j] = alo + ahi + biasS[tix];
            }
            float mc = s[0];
            #pragma unroll
            for (int j = 1; j < 16; j++) mc = fmaxf(mc, s[j]);
            float mnew  = fmaxf(m, mc);
            float alpha = fast_exp(m - mnew);
            l *= alpha;
            u64 alpha2 = pack2(alpha, alpha);
            #pragma unroll
            for (int d = 0; d < 12; d++) o2[d] = mul2(o2[d], alpha2);
            #pragma unroll
            for (int j = 0; j < 16; j++) {
                float p = fast_exp(s[j] - mnew);
                l += p;
                u64 p2 = pack2(p, p);
                const u64* vr = (const u64*)(vT + (c16*16 + j)*HD);
                #pragma unroll
                for (int d = 0; d < 12; d++) o2[d] = fma2(p2, vr[d], o2[d]);
            }
            m = mnew;
        }
        __syncthreads();
    }

    float inv = 1.f / l;
    float* op = oo + (size_t)(b*NN + n)*CC + h*HD;
    #pragma unroll
    for (int i = 0; i < 12; i++) {
        float lo, hi; unpack2(o2[i], lo, hi);
        op[2*i]   = lo * inv;
        op[2*i+1] = hi * inv;
    }
}

// ---------------- (o1+o2) @ W2 + bb -> [B,384,32,32] ----------------
__global__ __launch_bounds__(256) void k_proj() {
    int nt = blockIdx.x;     // 0..31
    int b  = blockIdx.y;     // 0..7
    int n0 = nt * 32;
    __shared__ __align__(16) float W2c[CC*64];     // 24 KB
    __shared__ float s[32*97];                     // padded rows, 12.4 KB

    int tid = threadIdx.x;
    for (int i = tid; i < 32*CC; i += 256) {
        int r = i / CC, c = i % CC;
        size_t idx = (size_t)(b*NN + n0 + r)*CC + c;
        s[r*97 + c] = g_o1[idx] + g_o2[idx];
    }

    int r     = tid & 31;
    int olane = tid >> 5;    // 0..7
    for (int ch = 0; ch < 6; ch++) {
        __syncthreads();
        for (int i = tid; i < CC*64; i += 256) {
            int c = i >> 6, j = i & 63;
            W2c[i] = g_W2[(size_t)c*DIM + ch*64 + j];
        }
        __syncthreads();
        #pragma unroll
        for (int jj = 0; jj < 8; jj++) {
            int j = olane + jj*8;
            float acc = g_bb[ch*64 + j];
            #pragma unroll 8
            for (int c = 0; c < CC; c++) acc += s[r*97 + c] * W2c[c*64 + j];
            g_small[((size_t)(b*DIM) + ch*64 + j)*NN + n0 + r] = acc;
        }
    }
}

// ---------------- bilinear x4 upsample, align_corners=True ----------------
__global__ __launch_bounds__(256) void k_upsample(float* __restrict__ out) {
    int plane = blockIdx.x;  // b*DIM + channel
    __shared__ float pl[NN];
    for (int i = threadIdx.x; i < NN; i += 256) pl[i] = g_small[(size_t)plane*NN + i];
    __syncthreads();

    const float sc = 31.f / 127.f;
    float* op = out + (size_t)plane*128*128;
    for (int idx = threadIdx.x; idx < 128*128; idx += 256) {
        int yo = idx >> 7, xo = idx & 127;
        float fy = yo * sc; int y0 = (int)fy; float wy = fy - y0; int y1 = min(y0+1, 31);
        float fx = xo * sc; int x0 = (int)fx; float wx = fx - x0; int x1 = min(x0+1, 31);
        float v00 = pl[y0*32+x0], v01 = pl[y0*32+x1];
        float v10 = pl[y1*32+x0], v11 = pl[y1*32+x1];
        float top = v00 + (v01 - v00)*wx;
        float bot = v10 + (v11 - v10)*wx;
        op[idx] = top + (bot - top)*wy;
    }
}

// ---------------- launch ----------------
extern "C" void kernel_launch(void* const* d_in, const int* in_sizes, int n_in,
                              void* d_out, int out_size) {
    const float* x        = (const float*)d_in[0];
    const float* w_le     = (const float*)d_in[1];
    const float* b_le     = (const float*)d_in[2];
    const float* bn_le    = (const float*)d_in[3];
    const float* w_max    = (const float*)d_in[4];
    const float* b_max    = (const float*)d_in[5];
    const float* bn_max   = (const float*)d_in[6];
    const float* w_avg    = (const float*)d_in[7];
    const float* b_avg    = (const float*)d_in[8];
    const float* bn_avg   = (const float*)d_in[9];
    const float* bias_tab = (const float*)d_in[10];
    const float* w_q      = (const float*)d_in[11];
    const float* w_kv     = (const float*)d_in[12];
    const float* w_proj   = (const float*)d_in[13];
    const float* b_proj   = (const float*)d_in[14];
    const float* w_out    = (const float*)d_in[15];
    const float* b_out    = (const float*)d_in[16];
    float* out = (float*)d_out;

    const float qscale = 0.20412414523193154f;   // 1/sqrt(24)

    k_prep  <<<DIM, CC>>>(w_proj, b_proj, w_out, b_out);
    k_stage1<<<dim3(4, DIM, BATCH), 256>>>(x, w_le);
    k_stage2<<<dim3(CC, BATCH), 256>>>(b_le, bn_le, w_max, b_max, bn_max, w_avg, b_avg, bn_avg);

    k_gemm_all<<<dim3(256, 5), 256>>>(w_q, w_kv, qscale);

    k_attn<<<dim3(8, NH*BATCH, 2), 128>>>(bias_tab);
    k_proj<<<dim3(32, BATCH), 256>>>();
    k_upsample<<<BATCH*DIM, 256>>>(out);
}

// round 4
// speedup vs baseline: 1.1113x; 1.0672x over previous
#include <cuda_runtime.h>

#define BATCH 8
#define DIM   384
#define CC    96
#define HIN   128
#define HQ    32
#define NN    1024
#define NH    4
#define HD    24
#define TBL   3969   // (2*32-1)^2
#define EPSI  1e-5f

typedef unsigned long long u64;

// ---------------- scratch (device globals: no allocation allowed) ----------------
__device__ __align__(16) float g_convp[BATCH*DIM*NN];
__device__ __align__(16) float g_pmax [BATCH*DIM*NN];
__device__ __align__(16) float g_pavg [BATCH*DIM*NN];
__device__ __align__(16) float g_xq   [BATCH*NN*CC];
__device__ __align__(16) float g_tmax [BATCH*NN*CC];
__device__ __align__(16) float g_tavg [BATCH*NN*CC];
__device__ __align__(16) float g_q    [BATCH*NN*CC];
__device__ __align__(16) float g_kv1  [BATCH*NN*2*CC];
__device__ __align__(16) float g_kv2  [BATCH*NN*2*CC];
__device__ __align__(16) float g_o1   [BATCH*NN*CC];
__device__ __align__(16) float g_o2   [BATCH*NN*CC];
__device__ __align__(16) float g_small[BATCH*DIM*NN];
__device__ __align__(16) float g_W2   [CC*DIM];
__device__ __align__(16) float g_bb   [DIM];

__device__ __forceinline__ float relu6f(float v) { return fminf(fmaxf(v, 0.f), 6.f); }

// ---- packed f32x2 helpers (Blackwell FFMA2 — PTX only, ptxas won't auto-fuse) ----
__device__ __forceinline__ u64 pack2(float a, float b) {
    u64 r; asm("mov.b64 %0, {%1, %2};" : "=l"(r) : "f"(a), "f"(b)); return r;
}
__device__ __forceinline__ void unpack2(u64 v, float& a, float& b) {
    asm("mov.b64 {%0, %1}, %2;" : "=f"(a), "=f"(b) : "l"(v));
}
__device__ __forceinline__ u64 fma2(u64 a, u64 b, u64 c) {
    u64 d; asm("fma.rn.f32x2 %0, %1, %2, %3;" : "=l"(d) : "l"(a), "l"(b), "l"(c)); return d;
}
__device__ __forceinline__ u64 mul2(u64 a, u64 b) {
    u64 d; asm("mul.rn.f32x2 %0, %1, %2;" : "=l"(d) : "l"(a), "l"(b)); return d;
}

// ---------------- fold w_proj @ w_out^T and biases ----------------
__global__ void k_prep(const float* __restrict__ wproj, const float* __restrict__ bproj,
                       const float* __restrict__ wout,  const float* __restrict__ bout) {
    int o = blockIdx.x;          // 0..383
    int i = threadIdx.x;         // 0..95
    float acc = 0.f;
    #pragma unroll 8
    for (int c = 0; c < CC; c++) acc += wproj[i*CC + c] * wout[o*CC + c];
    g_W2[i*DIM + o] = acc;
    if (i == 0) {
        float s = 0.f;
        for (int c = 0; c < CC; c++) s += bproj[c] * wout[o*CC + c];
        g_bb[o] = bout[o] + 2.f * s;
    }
}

// ---------------- stage1: per input channel d, per 4x4 block: max, avg, conv-partial ----------------
__global__ __launch_bounds__(256) void k_stage1(const float* __restrict__ x,
                                                const float* __restrict__ w_le) {
    int part = blockIdx.x;        // 0..3
    int d    = blockIdx.y;        // 0..383
    int b    = blockIdx.z;        // 0..7
    int p  = part*256 + threadIdx.x;   // 0..1023 position n
    int oh = p >> 5, ow = p & 31;

    const float* w = w_le + (size_t)(d >> 2)*64 + (size_t)(d & 3)*16;
    float wr[16];
    #pragma unroll
    for (int i = 0; i < 16; i++) wr[i] = w[i];

    const float* xp = x + (((size_t)(b*DIM + d)*HIN) + 4*oh)*HIN + 4*ow;
    float mx = -1e30f, sm = 0.f, cv = 0.f;
    #pragma unroll
    for (int kh = 0; kh < 4; kh++) {
        float4 v = *(const float4*)(xp + (size_t)kh*HIN);
        mx = fmaxf(mx, fmaxf(fmaxf(v.x, v.y), fmaxf(v.z, v.w)));
        sm += v.x + v.y + v.z + v.w;
        cv += v.x*wr[kh*4+0] + v.y*wr[kh*4+1] + v.z*wr[kh*4+2] + v.w*wr[kh*4+3];
    }
    size_t idx = (size_t)(b*DIM + d)*NN + p;
    g_pmax [idx] = mx;
    g_pavg [idx] = sm * (1.f/16.f);
    g_convp[idx] = cv;
}

// ---------------- stage2: combine groups of 4, bias+BN+ReLU6, transpose to [B,N,C] ----------------
__global__ __launch_bounds__(256) void k_stage2(
    const float* __restrict__ b_le,  const float* __restrict__ bn_le,
    const float* __restrict__ w_max, const float* __restrict__ b_max, const float* __restrict__ bn_max,
    const float* __restrict__ w_avg, const float* __restrict__ b_avg, const float* __restrict__ bn_avg)
{
    int c = blockIdx.x;          // 0..95
    int b = blockIdx.y;          // 0..7

    float sle = bn_le [0*CC+c] * rsqrtf(bn_le [3*CC+c] + EPSI);
    float tle = bn_le [1*CC+c] - bn_le [2*CC+c]*sle;
    float smx = bn_max[0*CC+c] * rsqrtf(bn_max[3*CC+c] + EPSI);
    float tmx = bn_max[1*CC+c] - bn_max[2*CC+c]*smx;
    float sav = bn_avg[0*CC+c] * rsqrtf(bn_avg[3*CC+c] + EPSI);
    float tav = bn_avg[1*CC+c] - bn_avg[2*CC+c]*sav;

    float wm0 = w_max[c*4+0], wm1 = w_max[c*4+1], wm2 = w_max[c*4+2], wm3 = w_max[c*4+3];
    float wa0 = w_avg[c*4+0], wa1 = w_avg[c*4+1], wa2 = w_avg[c*4+2], wa3 = w_avg[c*4+3];
    float ble = b_le[c], bmx = b_max[c], bav = b_avg[c];

    for (int n = threadIdx.x; n < NN; n += 256) {
        size_t base = (size_t)(b*DIM + 4*c)*NN + n;
        float conv = g_convp[base] + g_convp[base+NN] + g_convp[base+2*NN] + g_convp[base+3*NN];
        float xq = relu6f((conv + ble)*sle + tle);
        float pm = g_pmax[base]*wm0 + g_pmax[base+NN]*wm1 + g_pmax[base+2*NN]*wm2 + g_pmax[base+3*NN]*wm3;
        float tm = relu6f((pm + bmx)*smx + tmx);
        float pa = g_pavg[base]*wa0 + g_pavg[base+NN]*wa1 + g_pavg[base+2*NN]*wa2 + g_pavg[base+3*NN]*wa3;
        float ta = relu6f((pa + bav)*sav + tav);
        size_t oidx = (size_t)(b*NN + n)*CC + c;
        g_xq  [oidx] = xq;
        g_tmax[oidx] = tm;
        g_tavg[oidx] = ta;
    }
}

// ---------------- fused GEMMs: all 5 [8192,96]x[96,96] slices, 4x4 register blocking ----------------
__global__ __launch_bounds__(192) void k_gemm_all(const float* __restrict__ wq,
                                                  const float* __restrict__ wkv,
                                                  float qscale) {
    __shared__ __align__(16) float inT[CC*32];     // [k][r] transposed, 12 KB
    __shared__ __align__(16) float Ws [CC*CC];     // 36 KB (total 48 KB exactly)

    int slice = blockIdx.y;
    const float* in; float* out; const float* W; int Wld, col0, outld; float scale = 1.f;
    switch (slice) {
        case 0:  in = g_xq;   out = g_q;   W = wq;  Wld = CC;   col0 = 0;  outld = CC;   scale = qscale; break;
        case 1:  in = g_tmax; out = g_kv1; W = wkv; Wld = 2*CC; col0 = 0;  outld = 2*CC; break;
        case 2:  in = g_tmax; out = g_kv1; W = wkv; Wld = 2*CC; col0 = CC; outld = 2*CC; break;
        case 3:  in = g_tavg; out = g_kv2; W = wkv; Wld = 2*CC; col0 = 0;  outld = 2*CC; break;
        default: in = g_tavg; out = g_kv2; W = wkv; Wld = 2*CC; col0 = CC; outld = 2*CC; break;
    }

    int tid  = threadIdx.x;
    int row0 = blockIdx.x * 32;
    // transposed A tile: inT[k*32 + r]; conflict-free (bank = r % 32)
    for (int i = tid; i < 32*CC; i += 192) {
        int r = i & 31, k = i >> 5;
        inT[k*32 + r] = in[(size_t)(row0 + r)*CC + k];
    }
    for (int i = tid; i < CC*CC; i += 192) {
        int k = i / CC, j = i % CC;
        Ws[i] = W[(size_t)k*Wld + col0 + j];
    }
    __syncthreads();

    int rb = tid & 7;        // 0..7  (rows rb, rb+8, rb+16, rb+24)
    int cb = tid >> 3;       // 0..23 (cols cb*4 .. cb*4+3)

    float4 acc0 = {0,0,0,0}, acc1 = {0,0,0,0}, acc2 = {0,0,0,0}, acc3 = {0,0,0,0};
    #pragma unroll 4
    for (int k = 0; k < CC; k++) {
        float4 w = *(const float4*)(Ws + k*CC + cb*4);
        const float* ak = inT + k*32 + rb;
        float a0 = ak[0], a1 = ak[8], a2 = ak[16], a3 = ak[24];
        acc0.x += a0*w.x; acc0.y += a0*w.y; acc0.z += a0*w.z; acc0.w += a0*w.w;
        acc1.x += a1*w.x; acc1.y += a1*w.y; acc1.z += a1*w.z; acc1.w += a1*w.w;
        acc2.x += a2*w.x; acc2.y += a2*w.y; acc2.z += a2*w.z; acc2.w += a2*w.w;
        acc3.x += a3*w.x; acc3.y += a3*w.y; acc3.z += a3*w.z; acc3.w += a3*w.w;
    }
    float4 r0 = make_float4(acc0.x*scale, acc0.y*scale, acc0.z*scale, acc0.w*scale);
    float4 r1 = make_float4(acc1.x*scale, acc1.y*scale, acc1.z*scale, acc1.w*scale);
    float4 r2 = make_float4(acc2.x*scale, acc2.y*scale, acc2.z*scale, acc2.w*scale);
    float4 r3 = make_float4(acc3.x*scale, acc3.y*scale, acc3.z*scale, acc3.w*scale);
    *(float4*)(out + (size_t)(row0 + rb     )*outld + col0 + cb*4) = r0;
    *(float4*)(out + (size_t)(row0 + rb +  8)*outld + col0 + cb*4) = r1;
    *(float4*)(out + (size_t)(row0 + rb + 16)*outld + col0 + cb*4) = r2;
    *(float4*)(out + (size_t)(row0 + rb + 24)*outld + col0 + cb*4) = r3;
}

// ---------------- attention: 2 adjacent queries per lane, flash softmax, f32x2 math ----------------
__global__ __launch_bounds__(128) void k_attn(const float* __restrict__ bias_table) {
    int chunk = blockIdx.x;               // 0..3 : 256 query rows each
    int bh    = blockIdx.y;               // b*NH + h
    int br    = blockIdx.z;               // branch
    int b = bh >> 2, h = bh & 3;
    const float* kv = br ? g_kv2 : g_kv1;
    float*       oo = br ? g_o2  : g_o1;

    __shared__ __align__(16) float kT[32*HD];           // 3 KB
    __shared__ __align__(16) float vT[32*HD];           // 3 KB
    __shared__ float biasS[TBL];                        // 15.9 KB

    int tid = threadIdx.x;                // 0..127
    for (int i = tid; i < TBL; i += 128) biasS[i] = bias_table[(size_t)i*NH + h];

    int n0 = chunk*256 + tid*2;           // even query; pair (n0, n0+1) share row yn
    int yn = n0 >> 5, xn = n0 & 31;       // xn even => n0+1 stays in same row

    u64 qa[12], qb[12];
    {
        const u64* p = (const u64*)(g_q + (size_t)(b*NN + n0)*CC + h*HD);
        #pragma unroll
        for (int i = 0; i < 12; i++) qa[i] = p[i];
        p = (const u64*)(g_q + (size_t)(b*NN + n0 + 1)*CC + h*HD);
        #pragma unroll
        for (int i = 0; i < 12; i++) qb[i] = p[i];
    }

    float m0 = -1e30f, l0 = 0.f, m1 = -1e30f, l1 = 0.f;
    u64 oA[12], oB[12];
    #pragma unroll
    for (int i = 0; i < 12; i++) { oA[i] = 0ULL; oB[i] = 0ULL; }   // (0.f,0.f)

    __syncthreads();  // bias table ready

    for (int kt = 0; kt < 32; kt++) {
        for (int i = tid; i < 192; i += 128) {          // 32 keys x 6 float4
            int key = i / 6, g4 = i % 6;
            const float* rowp = kv + (size_t)(b*NN + kt*32 + key)*(2*CC) + h*HD;
            ((float4*)kT)[i] = ((const float4*)rowp)[g4];
            ((float4*)vT)[i] = ((const float4*)(rowp + CC))[g4];
        }
        __syncthreads();

        int base0 = (yn - kt + 31)*63 + xn + 31;        // ym == kt for this tile

        #pragma unroll
        for (int c16 = 0; c16 < 2; c16++) {
            float s0[16], s1[16];
            #pragma unroll
            for (int j = 0; j < 16; j++) {
                const u64* kr = (const u64*)(kT + (c16*16 + j)*HD);
                u64 aA = 0ULL, aB = 0ULL, bA = 0ULL, bB = 0ULL;
                #pragma unroll
                for (int d = 0; d < 6; d++)  { aA = fma2(qa[d], kr[d], aA); bA = fma2(qb[d], kr[d], bA); }
                #pragma unroll
                for (int d = 6; d < 12; d++) { aB = fma2(qa[d], kr[d], aB); bB = fma2(qb[d], kr[d], bB); }
                int xm = c16*16 + j;
                float x0, x1, x2, x3;
                unpack2(aA, x0, x1); unpack2(aB, x2, x3);
                s0[j] = (x0 + x1) + (x2 + x3) + biasS[base0 - xm];
                unpack2(bA, x0, x1); unpack2(bB, x2, x3);
                s1[j] = (x0 + x1) + (x2 + x3) + biasS[base0 + 1 - xm];
            }
            float mc0 = s0[0], mc1 = s1[0];
            #pragma unroll
            for (int j = 1; j < 16; j++) { mc0 = fmaxf(mc0, s0[j]); mc1 = fmaxf(mc1, s1[j]); }
            if (mc0 > m0) {
                float al = __expf(m0 - mc0); l0 *= al;
                u64 al2 = pack2(al, al);
                #pragma unroll
                for (int d = 0; d < 12; d++) oA[d] = mul2(oA[d], al2);
                m0 = mc0;
            }
            if (mc1 > m1) {
                float al = __expf(m1 - mc1); l1 *= al;
                u64 al2 = pack2(al, al);
                #pragma unroll
                for (int d = 0; d < 12; d++) oB[d] = mul2(oB[d], al2);
                m1 = mc1;
            }
            #pragma unroll
            for (int j = 0; j < 16; j++) {
                const u64* vr = (const u64*)(vT + (c16*16 + j)*HD);
                float p0 = __expf(s0[j] - m0); l0 += p0;
                float p1 = __expf(s1[j] - m1); l1 += p1;
                u64 p02 = pack2(p0, p0), p12 = pack2(p1, p1);
                #pragma unroll
                for (int d = 0; d < 12; d++) {
                    oA[d] = fma2(p02, vr[d], oA[d]);
                    oB[d] = fma2(p12, vr[d], oB[d]);
                }
            }
        }
        __syncthreads();
    }

    float i0 = 1.f / l0, i1 = 1.f / l1;
    u64 iv0 = pack2(i0, i0), iv1 = pack2(i1, i1);
    u64* op = (u64*)(oo + (size_t)(b*NN + n0)*CC + h*HD);
    #pragma unroll
    for (int d = 0; d < 12; d++) op[d] = mul2(oA[d], iv0);
    op = (u64*)(oo + (size_t)(b*NN + n0 + 1)*CC + h*HD);
    #pragma unroll
    for (int d = 0; d < 12; d++) op[d] = mul2(oB[d], iv1);
}

// ---------------- (o1+o2) @ W2 + bb -> [B,384,32,32] ----------------
__global__ __launch_bounds__(256) void k_proj() {
    int nt = blockIdx.x;     // 0..31
    int b  = blockIdx.y;     // 0..7
    int n0 = nt * 32;
    __shared__ __align__(16) float W2c[CC*64];     // 24 KB
    __shared__ float s[32*97];                     // padded rows, 12.4 KB

    int tid = threadIdx.x;
    for (int i = tid; i < 32*CC; i += 256) {
        int r = i / CC, c = i % CC;
        size_t idx = (size_t)(b*NN + n0 + r)*CC + c;
        s[r*97 + c] = g_o1[idx] + g_o2[idx];
    }

    int r     = tid & 31;
    int olane = tid >> 5;    // 0..7
    for (int ch = 0; ch < 6; ch++) {
        __syncthreads();
        for (int i = tid; i < CC*64; i += 256) {
            int c = i >> 6, j = i & 63;
            W2c[i] = g_W2[(size_t)c*DIM + ch*64 + j];
        }
        __syncthreads();
        #pragma unroll
        for (int jj = 0; jj < 8; jj++) {
            int j = olane + jj*8;
            float acc = g_bb[ch*64 + j];
            #pragma unroll 8
            for (int c = 0; c < CC; c++) acc += s[r*97 + c] * W2c[c*64 + j];
            g_small[((size_t)(b*DIM) + ch*64 + j)*NN + n0 + r] = acc;
        }
    }
}

// ---------------- bilinear x4 upsample, align_corners=True ----------------
__global__ __launch_bounds__(256) void k_upsample(float* __restrict__ out) {
    int plane = blockIdx.x;  // b*DIM + channel
    __shared__ float pl[NN];
    for (int i = threadIdx.x; i < NN; i += 256) pl[i] = g_small[(size_t)plane*NN + i];
    __syncthreads();

    const float sc = 31.f / 127.f;
    float* op = out + (size_t)plane*128*128;
    for (int idx = threadIdx.x; idx < 128*128; idx += 256) {
        int yo = idx >> 7, xo = idx & 127;
        float fy = yo * sc; int y0 = (int)fy; float wy = fy - y0; int y1 = min(y0+1, 31);
        float fx = xo * sc; int x0 = (int)fx; float wx = fx - x0; int x1 = min(x0+1, 31);
        float v00 = pl[y0*32+x0], v01 = pl[y0*32+x1];
        float v10 = pl[y1*32+x0], v11 = pl[y1*32+x1];
        float top = v00 + (v01 - v00)*wx;
        float bot = v10 + (v11 - v10)*wx;
        op[idx] = top + (bot - top)*wy;
    }
}

// ---------------- launch ----------------
extern "C" void kernel_launch(void* const* d_in, const int* in_sizes, int n_in,
                              void* d_out, int out_size) {
    const float* x        = (const float*)d_in[0];
    const float* w_le     = (const float*)d_in[1];
    const float* b_le     = (const float*)d_in[2];
    const float* bn_le    = (const float*)d_in[3];
    const float* w_max    = (const float*)d_in[4];
    const float* b_max    = (const float*)d_in[5];
    const float* bn_max   = (const float*)d_in[6];
    const float* w_avg    = (const float*)d_in[7];
    const float* b_avg    = (const float*)d_in[8];
    const float* bn_avg   = (const float*)d_in[9];
    const float* bias_tab = (const float*)d_in[10];
    const float* w_q      = (const float*)d_in[11];
    const float* w_kv     = (const float*)d_in[12];
    const float* w_proj   = (const float*)d_in[13];
    const float* b_proj   = (const float*)d_in[14];
    const float* w_out    = (const float*)d_in[15];
    const float* b_out    = (const float*)d_in[16];
    float* out = (float*)d_out;

    const float qscale = 0.20412414523193154f;   // 1/sqrt(24)

    k_prep  <<<DIM, CC>>>(w_proj, b_proj, w_out, b_out);
    k_stage1<<<dim3(4, DIM, BATCH), 256>>>(x, w_le);
    k_stage2<<<dim3(CC, BATCH), 256>>>(b_le, bn_le, w_max, b_max, bn_max, w_avg, b_avg, bn_avg);

    k_gemm_all<<<dim3(256, 5), 192>>>(w_q, w_kv, qscale);

    k_attn<<<dim3(4, NH*BATCH, 2), 128>>>(bias_tab);
    k_proj<<<dim3(32, BATCH), 256>>>();
    k_upsample<<<BATCH*DIM, 256>>>(out);
}

// round 5
// speedup vs baseline: 1.5164x; 1.3646x over previous
#include <cuda_runtime.h>

#define BATCH 8
#define DIM   384
#define CC    96
#define HIN   128
#define HQ    32
#define NN    1024
#define NH    4
#define HD    24
#define TBL   3969   // (2*32-1)^2
#define EPSI  1e-5f

typedef unsigned int u32;

// ---------------- scratch (device globals: no allocation allowed) ----------------
__device__ __align__(16) float g_convp[BATCH*DIM*NN];
__device__ __align__(16) float g_pmax [BATCH*DIM*NN];
__device__ __align__(16) float g_pavg [BATCH*DIM*NN];
__device__ __align__(16) float g_xq   [BATCH*NN*CC];
__device__ __align__(16) float g_tmax [BATCH*NN*CC];
__device__ __align__(16) float g_tavg [BATCH*NN*CC];
__device__ __align__(16) float g_q    [BATCH*NN*CC];
__device__ __align__(16) float g_kv1  [BATCH*NN*2*CC];
__device__ __align__(16) float g_kv2  [BATCH*NN*2*CC];
__device__ __align__(16) float g_o1   [BATCH*NN*CC];
__device__ __align__(16) float g_o2   [BATCH*NN*CC];
__device__ __align__(16) float g_small[BATCH*DIM*NN];
__device__ __align__(16) float g_W2   [CC*DIM];
__device__ __align__(16) float g_bb   [DIM];

__device__ __forceinline__ float relu6f(float v) { return fminf(fmaxf(v, 0.f), 6.f); }

// round fp32 -> tf32-representable fp32 (rna)
__device__ __forceinline__ float tf32r(float x) {
    u32 u; asm("cvt.rna.tf32.f32 %0, %1;" : "=r"(u) : "f"(x));
    return __uint_as_float(u);
}

// D += A * B  (m16n8k8, tf32 inputs as raw fp32 bits, fp32 accum)
__device__ __forceinline__ void mma8(float4& d, const u32 a0, const u32 a1, const u32 a2, const u32 a3,
                                     u32 b0, u32 b1) {
    asm volatile("mma.sync.aligned.m16n8k8.row.col.f32.tf32.tf32.f32 "
                 "{%0,%1,%2,%3},{%4,%5,%6,%7},{%8,%9},{%0,%1,%2,%3};"
                 : "+f"(d.x), "+f"(d.y), "+f"(d.z), "+f"(d.w)
                 : "r"(a0), "r"(a1), "r"(a2), "r"(a3), "r"(b0), "r"(b1));
}

// ---------------- fold w_proj @ w_out^T and biases ----------------
__global__ void k_prep(const float* __restrict__ wproj, const float* __restrict__ bproj,
                       const float* __restrict__ wout,  const float* __restrict__ bout) {
    int o = blockIdx.x;          // 0..383
    int i = threadIdx.x;         // 0..95
    float acc = 0.f;
    #pragma unroll 8
    for (int c = 0; c < CC; c++) acc += wproj[i*CC + c] * wout[o*CC + c];
    g_W2[i*DIM + o] = acc;
    if (i == 0) {
        float s = 0.f;
        for (int c = 0; c < CC; c++) s += bproj[c] * wout[o*CC + c];
        g_bb[o] = bout[o] + 2.f * s;
    }
}

// ---------------- stage1: per input channel d, per 4x4 block: max, avg, conv-partial ----------------
__global__ __launch_bounds__(256) void k_stage1(const float* __restrict__ x,
                                                const float* __restrict__ w_le) {
    int part = blockIdx.x;        // 0..3
    int d    = blockIdx.y;        // 0..383
    int b    = blockIdx.z;        // 0..7
    int p  = part*256 + threadIdx.x;   // 0..1023 position n
    int oh = p >> 5, ow = p & 31;

    const float* w = w_le + (size_t)(d >> 2)*64 + (size_t)(d & 3)*16;
    float wr[16];
    #pragma unroll
    for (int i = 0; i < 16; i++) wr[i] = w[i];

    const float* xp = x + (((size_t)(b*DIM + d)*HIN) + 4*oh)*HIN + 4*ow;
    float mx = -1e30f, sm = 0.f, cv = 0.f;
    #pragma unroll
    for (int kh = 0; kh < 4; kh++) {
        float4 v = *(const float4*)(xp + (size_t)kh*HIN);
        mx = fmaxf(mx, fmaxf(fmaxf(v.x, v.y), fmaxf(v.z, v.w)));
        sm += v.x + v.y + v.z + v.w;
        cv += v.x*wr[kh*4+0] + v.y*wr[kh*4+1] + v.z*wr[kh*4+2] + v.w*wr[kh*4+3];
    }
    size_t idx = (size_t)(b*DIM + d)*NN + p;
    g_pmax [idx] = mx;
    g_pavg [idx] = sm * (1.f/16.f);
    g_convp[idx] = cv;
}

// ---------------- stage2: combine groups of 4, bias+BN+ReLU6, transpose to [B,N,C] ----------------
__global__ __launch_bounds__(256) void k_stage2(
    const float* __restrict__ b_le,  const float* __restrict__ bn_le,
    const float* __restrict__ w_max, const float* __restrict__ b_max, const float* __restrict__ bn_max,
    const float* __restrict__ w_avg, const float* __restrict__ b_avg, const float* __restrict__ bn_avg)
{
    int c = blockIdx.x;          // 0..95
    int b = blockIdx.y;          // 0..7

    float sle = bn_le [0*CC+c] * rsqrtf(bn_le [3*CC+c] + EPSI);
    float tle = bn_le [1*CC+c] - bn_le [2*CC+c]*sle;
    float smx = bn_max[0*CC+c] * rsqrtf(bn_max[3*CC+c] + EPSI);
    float tmx = bn_max[1*CC+c] - bn_max[2*CC+c]*smx;
    float sav = bn_avg[0*CC+c] * rsqrtf(bn_avg[3*CC+c] + EPSI);
    float tav = bn_avg[1*CC+c] - bn_avg[2*CC+c]*sav;

    float wm0 = w_max[c*4+0], wm1 = w_max[c*4+1], wm2 = w_max[c*4+2], wm3 = w_max[c*4+3];
    float wa0 = w_avg[c*4+0], wa1 = w_avg[c*4+1], wa2 = w_avg[c*4+2], wa3 = w_avg[c*4+3];
    float ble = b_le[c], bmx = b_max[c], bav = b_avg[c];

    for (int n = threadIdx.x; n < NN; n += 256) {
        size_t base = (size_t)(b*DIM + 4*c)*NN + n;
        float conv = g_convp[base] + g_convp[base+NN] + g_convp[base+2*NN] + g_convp[base+3*NN];
        float xq = relu6f((conv + ble)*sle + tle);
        float pm = g_pmax[base]*wm0 + g_pmax[base+NN]*wm1 + g_pmax[base+2*NN]*wm2 + g_pmax[base+3*NN]*wm3;
        float tm = relu6f((pm + bmx)*smx + tmx);
        float pa = g_pavg[base]*wa0 + g_pavg[base+NN]*wa1 + g_pavg[base+2*NN]*wa2 + g_pavg[base+3*NN]*wa3;
        float ta = relu6f((pa + bav)*sav + tav);
        size_t oidx = (size_t)(b*NN + n)*CC + c;
        g_xq  [oidx] = xq;
        g_tmax[oidx] = tm;
        g_tavg[oidx] = ta;
    }
}

// ---------------- fused GEMMs: all 5 [8192,96]x[96,96] slices, 4x4 register blocking ----------------
// epilogue rounds outputs to tf32 (rna) so the attention mma's truncation is exact.
__global__ __launch_bounds__(192) void k_gemm_all(const float* __restrict__ wq,
                                                  const float* __restrict__ wkv,
                                                  float qscale) {
    __shared__ __align__(16) float inT[CC*32];     // [k][r] transposed, 12 KB
    __shared__ __align__(16) float Ws [CC*CC];     // 36 KB (total 48 KB exactly)

    int slice = blockIdx.y;
    const float* in; float* out; const float* W; int Wld, col0, outld; float scale = 1.f;
    switch (slice) {
        case 0:  in = g_xq;   out = g_q;   W = wq;  Wld = CC;   col0 = 0;  outld = CC;   scale = qscale; break;
        case 1:  in = g_tmax; out = g_kv1; W = wkv; Wld = 2*CC; col0 = 0;  outld = 2*CC; break;
        case 2:  in = g_tmax; out = g_kv1; W = wkv; Wld = 2*CC; col0 = CC; outld = 2*CC; break;
        case 3:  in = g_tavg; out = g_kv2; W = wkv; Wld = 2*CC; col0 = 0;  outld = 2*CC; break;
        default: in = g_tavg; out = g_kv2; W = wkv; Wld = 2*CC; col0 = CC; outld = 2*CC; break;
    }

    int tid  = threadIdx.x;
    int row0 = blockIdx.x * 32;
    for (int i = tid; i < 32*CC; i += 192) {
        int r = i & 31, k = i >> 5;
        inT[k*32 + r] = in[(size_t)(row0 + r)*CC + k];
    }
    for (int i = tid; i < CC*CC; i += 192) {
        int k = i / CC, j = i % CC;
        Ws[i] = W[(size_t)k*Wld + col0 + j];
    }
    __syncthreads();

    int rb = tid & 7;        // rows rb, rb+8, rb+16, rb+24
    int cb = tid >> 3;       // cols cb*4 .. cb*4+3

    float4 acc0 = {0,0,0,0}, acc1 = {0,0,0,0}, acc2 = {0,0,0,0}, acc3 = {0,0,0,0};
    #pragma unroll 4
    for (int k = 0; k < CC; k++) {
        float4 w = *(const float4*)(Ws + k*CC + cb*4);
        const float* ak = inT + k*32 + rb;
        float a0 = ak[0], a1 = ak[8], a2 = ak[16], a3 = ak[24];
        acc0.x += a0*w.x; acc0.y += a0*w.y; acc0.z += a0*w.z; acc0.w += a0*w.w;
        acc1.x += a1*w.x; acc1.y += a1*w.y; acc1.z += a1*w.z; acc1.w += a1*w.w;
        acc2.x += a2*w.x; acc2.y += a2*w.y; acc2.z += a2*w.z; acc2.w += a2*w.w;
        acc3.x += a3*w.x; acc3.y += a3*w.y; acc3.z += a3*w.z; acc3.w += a3*w.w;
    }
    float4 r0 = make_float4(tf32r(acc0.x*scale), tf32r(acc0.y*scale), tf32r(acc0.z*scale), tf32r(acc0.w*scale));
    float4 r1 = make_float4(tf32r(acc1.x*scale), tf32r(acc1.y*scale), tf32r(acc1.z*scale), tf32r(acc1.w*scale));
    float4 r2 = make_float4(tf32r(acc2.x*scale), tf32r(acc2.y*scale), tf32r(acc2.z*scale), tf32r(acc2.w*scale));
    float4 r3 = make_float4(tf32r(acc3.x*scale), tf32r(acc3.y*scale), tf32r(acc3.z*scale), tf32r(acc3.w*scale));
    *(float4*)(out + (size_t)(row0 + rb     )*outld + col0 + cb*4) = r0;
    *(float4*)(out + (size_t)(row0 + rb +  8)*outld + col0 + cb*4) = r1;
    *(float4*)(out + (size_t)(row0 + rb + 16)*outld + col0 + cb*4) = r2;
    *(float4*)(out + (size_t)(row0 + rb + 24)*outld + col0 + cb*4) = r3;
}

// ---------------- attention: warp-MMA (tf32) flash attention ----------------
// warp = 16 queries; block = 8 warps = 128 queries for one (b,h,branch).
// Per 32-key tile: S = Q K^T (12 mma), bias+online softmax in fp32, O += P V (12 mma)
// with the S-fragment reused directly as PV A-fragment (V rows permuted by tau).
__global__ __launch_bounds__(256) void k_attn(const float* __restrict__ bias_table) {
    int chunk = blockIdx.x;               // 0..7 : 128 queries
    int bh    = blockIdx.y;               // b*NH + h
    int br    = blockIdx.z;               // branch
    int b = bh >> 2, h = bh & 3;
    const float* kv = br ? g_kv2 : g_kv1;
    float*       oo = br ? g_o2  : g_o1;

    __shared__ __align__(16) float kT[32*HD];           // 3 KB  [key][dim]
    __shared__ __align__(16) float vT[32*HD];           // 3 KB  [key][dim]
    __shared__ float biasS[TBL];                        // 15.9 KB

    int tid  = threadIdx.x;
    int warp = tid >> 5, lane = tid & 31;
    int gr = lane >> 2, tg = lane & 3;                  // groupID, threadID-in-group

    for (int i = tid; i < TBL; i += 256) biasS[i] = bias_table[(size_t)i*NH + h];

    int q0  = chunk*128 + warp*16;        // 16 contiguous queries; q0%32 in {0,16}
    int yn  = q0 >> 5;                    // image row of all 16 queries
    int xq0 = q0 & 31;

    // Q fragments (rows q0+gr / q0+gr+8, cols k8*8+tg / +4), loaded once
    u32 qa[3][4];
    {
        const float* qr0 = g_q + (size_t)(b*NN + q0 + gr)*CC + h*HD;
        const float* qr1 = qr0 + 8*CC;
        #pragma unroll
        for (int k8 = 0; k8 < 3; k8++) {
            qa[k8][0] = __float_as_uint(qr0[k8*8 + tg]);
            qa[k8][1] = __float_as_uint(qr1[k8*8 + tg]);
            qa[k8][2] = __float_as_uint(qr0[k8*8 + tg + 4]);
            qa[k8][3] = __float_as_uint(qr1[k8*8 + tg + 4]);
        }
    }

    float4 ot[3];
    #pragma unroll
    for (int t = 0; t < 3; t++) ot[t] = make_float4(0.f, 0.f, 0.f, 0.f);
    float m0 = -1e30f, m1 = -1e30f, l0 = 0.f, l1 = 0.f;

    for (int kt = 0; kt < 32; kt++) {
        // cooperative tile load: 32 keys x 24 floats (k and v)
        for (int i = tid; i < 384; i += 256) {
            int ii  = (i < 192) ? i : i - 192;
            int key = ii / 6, g4 = ii % 6;
            const float* rowp = kv + (size_t)(b*NN + kt*32 + key)*(2*CC) + h*HD + ((i < 192) ? 0 : CC);
            ((float4*)(i < 192 ? kT : vT))[ii] = ((const float4*)rowp)[g4];
        }
        __syncthreads();

        // S = Q K^T   (4 n8-tiles x 3 k8-steps)
        float4 st[4];
        #pragma unroll
        for (int t = 0; t < 4; t++) {
            float4 s = make_float4(0.f, 0.f, 0.f, 0.f);
            const float* kb = kT + (t*8 + gr)*HD;
            #pragma unroll
            for (int k8 = 0; k8 < 3; k8++) {
                u32 b0 = __float_as_uint(kb[k8*8 + tg]);
                u32 b1 = __float_as_uint(kb[k8*8 + tg + 4]);
                mma8(s, qa[k8][0], qa[k8][1], qa[k8][2], qa[k8][3], b0, b1);
            }
            st[t] = s;
        }

        // + relative position bias (ym == kt for the whole tile)
        int Cb = (yn - kt + 31)*63 + xq0 + 31;
        #pragma unroll
        for (int t = 0; t < 4; t++) {
            int col = t*8 + 2*tg;
            st[t].x += biasS[Cb + gr - col];
            st[t].y += biasS[Cb + gr - col - 1];
            st[t].z += biasS[Cb + gr + 8 - col];
            st[t].w += biasS[Cb + gr + 8 - col - 1];
        }

        // row-max (within lane, then across the 4 lanes of the quad)
        float rm0 = fmaxf(fmaxf(st[0].x, st[0].y), fmaxf(st[1].x, st[1].y));
        rm0 = fmaxf(rm0, fmaxf(fmaxf(st[2].x, st[2].y), fmaxf(st[3].x, st[3].y)));
        float rm1 = fmaxf(fmaxf(st[0].z, st[0].w), fmaxf(st[1].z, st[1].w));
        rm1 = fmaxf(rm1, fmaxf(fmaxf(st[2].z, st[2].w), fmaxf(st[3].z, st[3].w)));
        rm0 = fmaxf(rm0, __shfl_xor_sync(0xFFFFFFFFu, rm0, 1));
        rm0 = fmaxf(rm0, __shfl_xor_sync(0xFFFFFFFFu, rm0, 2));
        rm1 = fmaxf(rm1, __shfl_xor_sync(0xFFFFFFFFu, rm1, 1));
        rm1 = fmaxf(rm1, __shfl_xor_sync(0xFFFFFFFFu, rm1, 2));

        float mn0 = fmaxf(m0, rm0), mn1 = fmaxf(m1, rm1);
        float a0 = __expf(m0 - mn0), a1 = __expf(m1 - mn1);
        m0 = mn0; m1 = mn1;
        l0 *= a0; l1 *= a1;
        #pragma unroll
        for (int t = 0; t < 3; t++) {
            ot[t].x *= a0; ot[t].y *= a0; ot[t].z *= a1; ot[t].w *= a1;
        }

        // P = exp(S - m); accumulate partial row sums
        #pragma unroll
        for (int t = 0; t < 4; t++) {
            st[t].x = __expf(st[t].x - m0); st[t].y = __expf(st[t].y - m0);
            st[t].z = __expf(st[t].z - m1); st[t].w = __expf(st[t].w - m1);
            l0 += st[t].x + st[t].y;
            l1 += st[t].z + st[t].w;
        }

        // O += P V  : A-frag = {x,z,y,w} of st[g]; V rows permuted (tau)
        #pragma unroll
        for (int g = 0; g < 4; g++) {
            u32 pa0 = __float_as_uint(st[g].x);
            u32 pa1 = __float_as_uint(st[g].z);
            u32 pa2 = __float_as_uint(st[g].y);
            u32 pa3 = __float_as_uint(st[g].w);
            const float* v0 = vT + (g*8 + 2*tg)*HD;      // tau(tg)   = 2*tg
            const float* v1 = v0 + HD;                   // tau(tg+4) = 2*tg+1
            #pragma unroll
            for (int t = 0; t < 3; t++) {
                u32 b0 = __float_as_uint(v0[t*8 + gr]);
                u32 b1 = __float_as_uint(v1[t*8 + gr]);
                mma8(ot[t], pa0, pa1, pa2, pa3, b0, b1);
            }
        }
        __syncthreads();
    }

    // normalize (row sums live split across the quad) and store
    l0 += __shfl_xor_sync(0xFFFFFFFFu, l0, 1);
    l0 += __shfl_xor_sync(0xFFFFFFFFu, l0, 2);
    l1 += __shfl_xor_sync(0xFFFFFFFFu, l1, 1);
    l1 += __shfl_xor_sync(0xFFFFFFFFu, l1, 2);
    float i0 = 1.f / l0, i1 = 1.f / l1;

    float* or0 = oo + (size_t)(b*NN + q0 + gr)*CC + h*HD;
    float* or1 = or0 + 8*CC;
    #pragma unroll
    for (int t = 0; t < 3; t++) {
        *(float2*)(or0 + t*8 + 2*tg) = make_float2(ot[t].x*i0, ot[t].y*i0);
        *(float2*)(or1 + t*8 + 2*tg) = make_float2(ot[t].z*i1, ot[t].w*i1);
    }
}

// ---------------- (o1+o2) @ W2 + bb -> [B,384,32,32] ----------------
__global__ __launch_bounds__(256) void k_proj() {
    int nt = blockIdx.x;     // 0..31
    int b  = blockIdx.y;     // 0..7
    int n0 = nt * 32;
    __shared__ __align__(16) float W2c[CC*64];     // 24 KB
    __shared__ float s[32*97];                     // padded rows, 12.4 KB

    int tid = threadIdx.x;
    for (int i = tid; i < 32*CC; i += 256) {
        int r = i / CC, c = i % CC;
        size_t idx = (size_t)(b*NN + n0 + r)*CC + c;
        s[r*97 + c] = g_o1[idx] + g_o2[idx];
    }

    int r     = tid & 31;
    int olane = tid >> 5;    // 0..7
    for (int ch = 0; ch < 6; ch++) {
        __syncthreads();
        for (int i = tid; i < CC*64; i += 256) {
            int c = i >> 6, j = i & 63;
            W2c[i] = g_W2[(size_t)c*DIM + ch*64 + j];
        }
        __syncthreads();
        #pragma unroll
        for (int jj = 0; jj < 8; jj++) {
            int j = olane + jj*8;
            float acc = g_bb[ch*64 + j];
            #pragma unroll 8
            for (int c = 0; c < CC; c++) acc += s[r*97 + c] * W2c[c*64 + j];
            g_small[((size_t)(b*DIM) + ch*64 + j)*NN + n0 + r] = acc;
        }
    }
}

// ---------------- bilinear x4 upsample, align_corners=True ----------------
__global__ __launch_bounds__(256) void k_upsample(float* __restrict__ out) {
    int plane = blockIdx.x;  // b*DIM + channel
    __shared__ float pl[NN];
    for (int i = threadIdx.x; i < NN; i += 256) pl[i] = g_small[(size_t)plane*NN + i];
    __syncthreads();

    const float sc = 31.f / 127.f;
    float* op = out + (size_t)plane*128*128;
    for (int idx = threadIdx.x; idx < 128*128; idx += 256) {
        int yo = idx >> 7, xo = idx & 127;
        float fy = yo * sc; int y0 = (int)fy; float wy = fy - y0; int y1 = min(y0+1, 31);
        float fx = xo * sc; int x0 = (int)fx; float wx = fx - x0; int x1 = min(x0+1, 31);
        float v00 = pl[y0*32+x0], v01 = pl[y0*32+x1];
        float v10 = pl[y1*32+x0], v11 = pl[y1*32+x1];
        float top = v00 + (v01 - v00)*wx;
        float bot = v10 + (v11 - v10)*wx;
        op[idx] = top + (bot - top)*wy;
    }
}

// ---------------- launch ----------------
extern "C" void kernel_launch(void* const* d_in, const int* in_sizes, int n_in,
                              void* d_out, int out_size) {
    const float* x        = (const float*)d_in[0];
    const float* w_le     = (const float*)d_in[1];
    const float* b_le     = (const float*)d_in[2];
    const float* bn_le    = (const float*)d_in[3];
    const float* w_max    = (const float*)d_in[4];
    const float* b_max    = (const float*)d_in[5];
    const float* bn_max   = (const float*)d_in[6];
    const float* w_avg    = (const float*)d_in[7];
    const float* b_avg    = (const float*)d_in[8];
    const float* bn_avg   = (const float*)d_in[9];
    const float* bias_tab = (const float*)d_in[10];
    const float* w_q      = (const float*)d_in[11];
    const float* w_kv     = (const float*)d_in[12];
    const float* w_proj   = (const float*)d_in[13];
    const float* b_proj   = (const float*)d_in[14];
    const float* w_out    = (const float*)d_in[15];
    const float* b_out    = (const float*)d_in[16];
    float* out = (float*)d_out;

    const float qscale = 0.20412414523193154f;   // 1/sqrt(24)

    k_prep  <<<DIM, CC>>>(w_proj, b_proj, w_out, b_out);
    k_stage1<<<dim3(4, DIM, BATCH), 256>>>(x, w_le);
    k_stage2<<<dim3(CC, BATCH), 256>>>(b_le, bn_le, w_max, b_max, bn_max, w_avg, b_avg, bn_avg);

    k_gemm_all<<<dim3(256, 5), 192>>>(w_q, w_kv, qscale);

    k_attn<<<dim3(8, NH*BATCH, 2), 256>>>(bias_tab);
    k_proj<<<dim3(32, BATCH), 256>>>();
    k_upsample<<<BATCH*DIM, 256>>>(out);
}

// round 6
// speedup vs baseline: 1.5685x; 1.0343x over previous
#include <cuda_runtime.h>

#define BATCH 8
#define DIM   384
#define CC    96
#define HIN   128
#define HQ    32
#define NN    1024
#define NH    4
#define HD    24
#define TBL   3969   // (2*32-1)^2
#define EPSI  1e-5f

typedef unsigned int u32;

// ---------------- scratch (device globals: no allocation allowed) ----------------
__device__ __align__(16) float g_xq   [BATCH*NN*CC];
__device__ __align__(16) float g_tmax [BATCH*NN*CC];
__device__ __align__(16) float g_tavg [BATCH*NN*CC];
__device__ __align__(16) float g_q    [BATCH*NN*CC];
__device__ __align__(16) float g_kv1  [BATCH*NN*2*CC];
__device__ __align__(16) float g_kv2  [BATCH*NN*2*CC];
__device__ __align__(16) float g_o1   [BATCH*NN*CC];
__device__ __align__(16) float g_o2   [BATCH*NN*CC];
__device__ __align__(16) float g_small[BATCH*DIM*NN];
__device__ __align__(16) float g_W2   [CC*DIM];
__device__ __align__(16) float g_bb   [DIM];

__device__ __forceinline__ float relu6f(float v) { return fminf(fmaxf(v, 0.f), 6.f); }

// round fp32 -> tf32-representable fp32 (rna)
__device__ __forceinline__ float tf32r(float x) {
    u32 u; asm("cvt.rna.tf32.f32 %0, %1;" : "=r"(u) : "f"(x));
    return __uint_as_float(u);
}

// D += A * B  (m16n8k8, tf32 inputs as raw fp32 bits, fp32 accum)
__device__ __forceinline__ void mma8(float4& d, const u32 a0, const u32 a1, const u32 a2, const u32 a3,
                                     u32 b0, u32 b1) {
    asm volatile("mma.sync.aligned.m16n8k8.row.col.f32.tf32.tf32.f32 "
                 "{%0,%1,%2,%3},{%4,%5,%6,%7},{%8,%9},{%0,%1,%2,%3};"
                 : "+f"(d.x), "+f"(d.y), "+f"(d.z), "+f"(d.w)
                 : "r"(a0), "r"(a1), "r"(a2), "r"(a3), "r"(b0), "r"(b1));
}

// ---------------- fold w_proj @ w_out^T and biases ----------------
__global__ void k_prep(const float* __restrict__ wproj, const float* __restrict__ bproj,
                       const float* __restrict__ wout,  const float* __restrict__ bout) {
    int o = blockIdx.x;          // 0..383
    int i = threadIdx.x;         // 0..95
    float acc = 0.f;
    #pragma unroll 8
    for (int c = 0; c < CC; c++) acc += wproj[i*CC + c] * wout[o*CC + c];
    g_W2[i*DIM + o] = acc;
    if (i == 0) {
        float s = 0.f;
        for (int c = 0; c < CC; c++) s += bproj[c] * wout[o*CC + c];
        g_bb[o] = bout[o] + 2.f * s;
    }
}

// ---------------- fused stage1+2: conv4x4s4/maxpool4/avgpool4 + grouped combine + BN + ReLU6 ----------------
// block = 32 positions x 8 output channels; x read exactly once; outputs [B,N,C] with 32B-sector writes
__global__ __launch_bounds__(256) void k_stage12(
    const float* __restrict__ x,     const float* __restrict__ w_le,
    const float* __restrict__ b_le,  const float* __restrict__ bn_le,
    const float* __restrict__ w_max, const float* __restrict__ b_max, const float* __restrict__ bn_max,
    const float* __restrict__ w_avg, const float* __restrict__ b_avg, const float* __restrict__ bn_avg)
{
    int n0 = blockIdx.x * 32;     // 32 positions
    int c0 = blockIdx.y * 8;      // 8 output channels
    int b  = blockIdx.z;

    int lane = threadIdx.x & 31;  // position
    int wrp  = threadIdx.x >> 5;  // channel offset 0..7
    int c = c0 + wrp;
    int n = n0 + lane;
    int oh = n >> 5, ow = n & 31;

    __shared__ float wS[8*64];            // conv weights for the 8 channels
    __shared__ float oS[3][32][9];        // padded transpose-stage

    for (int i = threadIdx.x; i < 512; i += 256) wS[i] = w_le[(size_t)c0*64 + i];

    // BN folds (per warp: all lanes same c -> broadcast loads)
    float sle = bn_le [0*CC+c] * rsqrtf(bn_le [3*CC+c] + EPSI);
    float tle = bn_le [1*CC+c] - bn_le [2*CC+c]*sle;
    float smx = bn_max[0*CC+c] * rsqrtf(bn_max[3*CC+c] + EPSI);
    float tmx = bn_max[1*CC+c] - bn_max[2*CC+c]*smx;
    float sav = bn_avg[0*CC+c] * rsqrtf(bn_avg[3*CC+c] + EPSI);
    float tav = bn_avg[1*CC+c] - bn_avg[2*CC+c]*sav;
    float ble = b_le[c], bmx = b_max[c], bav = b_avg[c];
    __syncthreads();

    const float* wc = wS + wrp*64;
    const float* xp = x + (((size_t)(b*DIM + 4*c)*HIN) + 4*oh)*HIN + 4*ow;

    float cv = 0.f, pm = 0.f, pa = 0.f;
    #pragma unroll
    for (int i = 0; i < 4; i++) {
        const float* xpi = xp + (size_t)i*HIN*HIN;
        float mxi = -1e30f, smi = 0.f, cvi = 0.f;
        #pragma unroll
        for (int kh = 0; kh < 4; kh++) {
            float4 v = *(const float4*)(xpi + (size_t)kh*HIN);
            mxi = fmaxf(mxi, fmaxf(fmaxf(v.x, v.y), fmaxf(v.z, v.w)));
            smi += v.x + v.y + v.z + v.w;
            cvi += v.x*wc[i*16+kh*4+0] + v.y*wc[i*16+kh*4+1] + v.z*wc[i*16+kh*4+2] + v.w*wc[i*16+kh*4+3];
        }
        cv += cvi;
        pm += mxi * w_max[c*4+i];
        pa += smi * (1.f/16.f) * w_avg[c*4+i];
    }

    oS[0][lane][wrp] = relu6f((cv + ble)*sle + tle);
    oS[1][lane][wrp] = relu6f((pm + bmx)*smx + tmx);
    oS[2][lane][wrp] = relu6f((pa + bav)*sav + tav);
    __syncthreads();

    // remapped write: 8 consecutive tid -> 8 consecutive channels (32B sectors)
    int pos = threadIdx.x >> 3, cc = threadIdx.x & 7;
    size_t oidx = (size_t)(b*NN + n0 + pos)*CC + c0 + cc;
    g_xq  [oidx] = oS[0][pos][cc];
    g_tmax[oidx] = oS[1][pos][cc];
    g_tavg[oidx] = oS[2][pos][cc];
}

// ---------------- fused GEMMs: all 5 [8192,96]x[96,96] slices, 4x4 register blocking ----------------
// epilogue rounds outputs to tf32 (rna) so the attention mma's truncation is exact.
__global__ __launch_bounds__(192) void k_gemm_all(const float* __restrict__ wq,
                                                  const float* __restrict__ wkv,
                                                  float qscale) {
    __shared__ __align__(16) float inT[CC*32];     // [k][r] transposed, 12 KB
    __shared__ __align__(16) float Ws [CC*CC];     // 36 KB (total 48 KB exactly)

    int slice = blockIdx.y;
    const float* in; float* out; const float* W; int Wld, col0, outld; float scale = 1.f;
    switch (slice) {
        case 0:  in = g_xq;   out = g_q;   W = wq;  Wld = CC;   col0 = 0;  outld = CC;   scale = qscale; break;
        case 1:  in = g_tmax; out = g_kv1; W = wkv; Wld = 2*CC; col0 = 0;  outld = 2*CC; break;
        case 2:  in = g_tmax; out = g_kv1; W = wkv; Wld = 2*CC; col0 = CC; outld = 2*CC; break;
        case 3:  in = g_tavg; out = g_kv2; W = wkv; Wld = 2*CC; col0 = 0;  outld = 2*CC; break;
        default: in = g_tavg; out = g_kv2; W = wkv; Wld = 2*CC; col0 = CC; outld = 2*CC; break;
    }

    int tid  = threadIdx.x;
    int row0 = blockIdx.x * 32;
    for (int i = tid; i < 32*CC; i += 192) {
        int r = i & 31, k = i >> 5;
        inT[k*32 + r] = in[(size_t)(row0 + r)*CC + k];
    }
    for (int i = tid; i < CC*CC; i += 192) {
        int k = i / CC, j = i % CC;
        Ws[i] = W[(size_t)k*Wld + col0 + j];
    }
    __syncthreads();

    int rb = tid & 7;        // rows rb*4 .. rb*4+3 (consecutive -> float4 A loads)
    int cb = tid >> 3;       // cols cb*4 .. cb*4+3

    float4 acc0 = {0,0,0,0}, acc1 = {0,0,0,0}, acc2 = {0,0,0,0}, acc3 = {0,0,0,0};
    #pragma unroll 4
    for (int k = 0; k < CC; k++) {
        float4 w = *(const float4*)(Ws + k*CC + cb*4);
        float4 a = *(const float4*)(inT + k*32 + rb*4);
        acc0.x += a.x*w.x; acc0.y += a.x*w.y; acc0.z += a.x*w.z; acc0.w += a.x*w.w;
        acc1.x += a.y*w.x; acc1.y += a.y*w.y; acc1.z += a.y*w.z; acc1.w += a.y*w.w;
        acc2.x += a.z*w.x; acc2.y += a.z*w.y; acc2.z += a.z*w.z; acc2.w += a.z*w.w;
        acc3.x += a.w*w.x; acc3.y += a.w*w.y; acc3.z += a.w*w.z; acc3.w += a.w*w.w;
    }
    float4 r0 = make_float4(tf32r(acc0.x*scale), tf32r(acc0.y*scale), tf32r(acc0.z*scale), tf32r(acc0.w*scale));
    float4 r1 = make_float4(tf32r(acc1.x*scale), tf32r(acc1.y*scale), tf32r(acc1.z*scale), tf32r(acc1.w*scale));
    float4 r2 = make_float4(tf32r(acc2.x*scale), tf32r(acc2.y*scale), tf32r(acc2.z*scale), tf32r(acc2.w*scale));
    float4 r3 = make_float4(tf32r(acc3.x*scale), tf32r(acc3.y*scale), tf32r(acc3.z*scale), tf32r(acc3.w*scale));
    *(float4*)(out + (size_t)(row0 + rb*4    )*outld + col0 + cb*4) = r0;
    *(float4*)(out + (size_t)(row0 + rb*4 + 1)*outld + col0 + cb*4) = r1;
    *(float4*)(out + (size_t)(row0 + rb*4 + 2)*outld + col0 + cb*4) = r2;
    *(float4*)(out + (size_t)(row0 + rb*4 + 3)*outld + col0 + cb*4) = r3;
}

// ---------------- attention: warp-MMA (tf32) flash attention, double-buffered kv ----------------
__global__ __launch_bounds__(256) void k_attn(const float* __restrict__ bias_table) {
    int chunk = blockIdx.x;               // 0..7 : 128 queries
    int bh    = blockIdx.y;               // b*NH + h
    int br    = blockIdx.z;               // branch
    int b = bh >> 2, h = bh & 3;
    const float* kv = br ? g_kv2 : g_kv1;
    float*       oo = br ? g_o2  : g_o1;

    __shared__ __align__(16) float kT[2][32*HD];        // 6 KB  double-buffered
    __shared__ __align__(16) float vT[2][32*HD];        // 6 KB
    __shared__ float biasS[TBL];                        // 15.9 KB

    int tid  = threadIdx.x;
    int warp = tid >> 5, lane = tid & 31;
    int gr = lane >> 2, tg = lane & 3;                  // groupID, threadID-in-group

    for (int i = tid; i < TBL; i += 256) biasS[i] = bias_table[(size_t)i*NH + h];

    int q0  = chunk*128 + warp*16;        // 16 contiguous queries; q0%32 in {0,16}
    int yn  = q0 >> 5;
    int xq0 = q0 & 31;

    // Q fragments (rows q0+gr / q0+gr+8, cols k8*8+tg / +4), loaded once
    u32 qa[3][4];
    {
        const float* qr0 = g_q + (size_t)(b*NN + q0 + gr)*CC + h*HD;
        const float* qr1 = qr0 + 8*CC;
        #pragma unroll
        for (int k8 = 0; k8 < 3; k8++) {
            qa[k8][0] = __float_as_uint(qr0[k8*8 + tg]);
            qa[k8][1] = __float_as_uint(qr1[k8*8 + tg]);
            qa[k8][2] = __float_as_uint(qr0[k8*8 + tg + 4]);
            qa[k8][3] = __float_as_uint(qr1[k8*8 + tg + 4]);
        }
    }

    // tile loader: 32 keys x 24 floats of k and v into buffer bu
    auto prefetch = [&](int bu, int kt) {
        #pragma unroll
        for (int i = tid; i < 384; i += 256) {
            int ii  = (i < 192) ? i : i - 192;
            int key = ii / 6, g4 = ii % 6;
            const float* rowp = kv + (size_t)(b*NN + kt*32 + key)*(2*CC) + h*HD + ((i < 192) ? 0 : CC);
            ((float4*)(i < 192 ? kT[bu] : vT[bu]))[ii] = ((const float4*)rowp)[g4];
        }
    };

    float4 ot[3];
    #pragma unroll
    for (int t = 0; t < 3; t++) ot[t] = make_float4(0.f, 0.f, 0.f, 0.f);
    float m0 = -1e30f, m1 = -1e30f, l0 = 0.f, l1 = 0.f;

    prefetch(0, 0);
    __syncthreads();

    for (int kt = 0; kt < 32; kt++) {
        int cur = kt & 1;
        if (kt + 1 < 32) prefetch(cur ^ 1, kt + 1);   // overlap with compute below

        const float* kC = kT[cur];
        const float* vC = vT[cur];

        // S = Q K^T   (4 n8-tiles x 3 k8-steps)
        float4 st[4];
        #pragma unroll
        for (int t = 0; t < 4; t++) {
            float4 s = make_float4(0.f, 0.f, 0.f, 0.f);
            const float* kb = kC + (t*8 + gr)*HD;
            #pragma unroll
            for (int k8 = 0; k8 < 3; k8++) {
                u32 b0 = __float_as_uint(kb[k8*8 + tg]);
                u32 b1 = __float_as_uint(kb[k8*8 + tg + 4]);
                mma8(s, qa[k8][0], qa[k8][1], qa[k8][2], qa[k8][3], b0, b1);
            }
            st[t] = s;
        }

        // + relative position bias (ym == kt for the whole tile)
        int Cb = (yn - kt + 31)*63 + xq0 + 31;
        #pragma unroll
        for (int t = 0; t < 4; t++) {
            int col = t*8 + 2*tg;
            st[t].x += biasS[Cb + gr - col];
            st[t].y += biasS[Cb + gr - col - 1];
            st[t].z += biasS[Cb + gr + 8 - col];
            st[t].w += biasS[Cb + gr + 8 - col - 1];
        }

        // row-max
        float rm0 = fmaxf(fmaxf(st[0].x, st[0].y), fmaxf(st[1].x, st[1].y));
        rm0 = fmaxf(rm0, fmaxf(fmaxf(st[2].x, st[2].y), fmaxf(st[3].x, st[3].y)));
        float rm1 = fmaxf(fmaxf(st[0].z, st[0].w), fmaxf(st[1].z, st[1].w));
        rm1 = fmaxf(rm1, fmaxf(fmaxf(st[2].z, st[2].w), fmaxf(st[3].z, st[3].w)));
        rm0 = fmaxf(rm0, __shfl_xor_sync(0xFFFFFFFFu, rm0, 1));
        rm0 = fmaxf(rm0, __shfl_xor_sync(0xFFFFFFFFu, rm0, 2));
        rm1 = fmaxf(rm1, __shfl_xor_sync(0xFFFFFFFFu, rm1, 1));
        rm1 = fmaxf(rm1, __shfl_xor_sync(0xFFFFFFFFu, rm1, 2));

        float mn0 = fmaxf(m0, rm0), mn1 = fmaxf(m1, rm1);
        float a0 = __expf(m0 - mn0), a1 = __expf(m1 - mn1);
        m0 = mn0; m1 = mn1;
        l0 *= a0; l1 *= a1;
        #pragma unroll
        for (int t = 0; t < 3; t++) {
            ot[t].x *= a0; ot[t].y *= a0; ot[t].z *= a1; ot[t].w *= a1;
        }

        // P = exp(S - m); accumulate partial row sums
        #pragma unroll
        for (int t = 0; t < 4; t++) {
            st[t].x = __expf(st[t].x - m0); st[t].y = __expf(st[t].y - m0);
            st[t].z = __expf(st[t].z - m1); st[t].w = __expf(st[t].w - m1);
            l0 += st[t].x + st[t].y;
            l1 += st[t].z + st[t].w;
        }

        // O += P V  : A-frag = {x,z,y,w} of st[g]; V rows permuted (tau)
        #pragma unroll
        for (int g = 0; g < 4; g++) {
            u32 pa0 = __float_as_uint(st[g].x);
            u32 pa1 = __float_as_uint(st[g].z);
            u32 pa2 = __float_as_uint(st[g].y);
            u32 pa3 = __float_as_uint(st[g].w);
            const float* v0 = vC + (g*8 + 2*tg)*HD;      // tau(tg)   = 2*tg
            const float* v1 = v0 + HD;                   // tau(tg+4) = 2*tg+1
            #pragma unroll
            for (int t = 0; t < 3; t++) {
                u32 b0 = __float_as_uint(v0[t*8 + gr]);
                u32 b1 = __float_as_uint(v1[t*8 + gr]);
                mma8(ot[t], pa0, pa1, pa2, pa3, b0, b1);
            }
        }
        __syncthreads();
    }

    l0 += __shfl_xor_sync(0xFFFFFFFFu, l0, 1);
    l0 += __shfl_xor_sync(0xFFFFFFFFu, l0, 2);
    l1 += __shfl_xor_sync(0xFFFFFFFFu, l1, 1);
    l1 += __shfl_xor_sync(0xFFFFFFFFu, l1, 2);
    float i0 = 1.f / l0, i1 = 1.f / l1;

    float* or0 = oo + (size_t)(b*NN + q0 + gr)*CC + h*HD;
    float* or1 = or0 + 8*CC;
    #pragma unroll
    for (int t = 0; t < 3; t++) {
        *(float2*)(or0 + t*8 + 2*tg) = make_float2(ot[t].x*i0, ot[t].y*i0);
        *(float2*)(or1 + t*8 + 2*tg) = make_float2(ot[t].z*i1, ot[t].w*i1);
    }
}

// ---------------- (o1+o2) @ W2 + bb -> [B,384,32,32] ----------------
__global__ __launch_bounds__(256) void k_proj() {
    int nt = blockIdx.x;     // 0..31
    int b  = blockIdx.y;     // 0..7
    int n0 = nt * 32;
    __shared__ __align__(16) float W2c[CC*64];     // 24 KB
    __shared__ float s[32*97];                     // padded rows, 12.4 KB

    int tid = threadIdx.x;
    for (int i = tid; i < 32*CC; i += 256) {
        int r = i / CC, c = i % CC;
        size_t idx = (size_t)(b*NN + n0 + r)*CC + c;
        s[r*97 + c] = g_o1[idx] + g_o2[idx];
    }

    int r     = tid & 31;
    int olane = tid >> 5;    // 0..7
    for (int ch = 0; ch < 6; ch++) {
        __syncthreads();
        for (int i = tid; i < CC*64; i += 256) {
            int c = i >> 6, j = i & 63;
            W2c[i] = g_W2[(size_t)c*DIM + ch*64 + j];
        }
        __syncthreads();
        #pragma unroll
        for (int jj = 0; jj < 8; jj++) {
            int j = olane + jj*8;
            float acc = g_bb[ch*64 + j];
            #pragma unroll 8
            for (int c = 0; c < CC; c++) acc += s[r*97 + c] * W2c[c*64 + j];
            g_small[((size_t)(b*DIM) + ch*64 + j)*NN + n0 + r] = acc;
        }
    }
}

// ---------------- bilinear x4 upsample, align_corners=True ----------------
__global__ __launch_bounds__(256) void k_upsample(float* __restrict__ out) {
    int plane = blockIdx.x;  // b*DIM + channel
    __shared__ float pl[NN];
    for (int i = threadIdx.x; i < NN; i += 256) pl[i] = g_small[(size_t)plane*NN + i];
    __syncthreads();

    const float sc = 31.f / 127.f;
    float* op = out + (size_t)plane*128*128;
    for (int idx = threadIdx.x; idx < 128*128; idx += 256) {
        int yo = idx >> 7, xo = idx & 127;
        float fy = yo * sc; int y0 = (int)fy; float wy = fy - y0; int y1 = min(y0+1, 31);
        float fx = xo * sc; int x0 = (int)fx; float wx = fx - x0; int x1 = min(x0+1, 31);
        float v00 = pl[y0*32+x0], v01 = pl[y0*32+x1];
        float v10 = pl[y1*32+x0], v11 = pl[y1*32+x1];
        float top = v00 + (v01 - v00)*wx;
        float bot = v10 + (v11 - v10)*wx;
        op[idx] = top + (bot - top)*wy;
    }
}

// ---------------- launch ----------------
extern "C" void kernel_launch(void* const* d_in, const int* in_sizes, int n_in,
                              void* d_out, int out_size) {
    const float* x        = (const float*)d_in[0];
    const float* w_le     = (const float*)d_in[1];
    const float* b_le     = (const float*)d_in[2];
    const float* bn_le    = (const float*)d_in[3];
    const float* w_max    = (const float*)d_in[4];
    const float* b_max    = (const float*)d_in[5];
    const float* bn_max   = (const float*)d_in[6];
    const float* w_avg    = (const float*)d_in[7];
    const float* b_avg    = (const float*)d_in[8];
    const float* bn_avg   = (const float*)d_in[9];
    const float* bias_tab = (const float*)d_in[10];
    const float* w_q      = (const float*)d_in[11];
    const float* w_kv     = (const float*)d_in[12];
    const float* w_proj   = (const float*)d_in[13];
    const float* b_proj   = (const float*)d_in[14];
    const float* w_out    = (const float*)d_in[15];
    const float* b_out    = (const float*)d_in[16];
    float* out = (float*)d_out;

    const float qscale = 0.20412414523193154f;   // 1/sqrt(24)

    k_prep   <<<DIM, CC>>>(w_proj, b_proj, w_out, b_out);
    k_stage12<<<dim3(32, 12, BATCH), 256>>>(x, w_le, b_le, bn_le,
                                            w_max, b_max, bn_max, w_avg, b_avg, bn_avg);

    k_gemm_all<<<dim3(256, 5), 192>>>(w_q, w_kv, qscale);

    k_attn<<<dim3(8, NH*BATCH, 2), 256>>>(bias_tab);
    k_proj<<<dim3(32, BATCH), 256>>>();
    k_upsample<<<BATCH*DIM, 256>>>(out);
}